// round 9
// baseline (speedup 1.0000x reference)
#include <cuda_runtime.h>
#include <cuda_bf16.h>
#include <math.h>

#define Bn 4
#define Pp 4
#define Cc 64
#define NH 8
#define Hh 128
#define Wd 128
#define HW 16384

// scratch (no cudaMalloc allowed)
__device__ float g_mb[16 * HW];   // mask bias per (b,p,pos)

// ---------------------------------------------------------------------------
// helpers
// ---------------------------------------------------------------------------
__device__ __forceinline__ void bsplit(float f, __nv_bfloat16& h, __nv_bfloat16& l) {
    h = __float2bfloat16(f);
    l = __float2bfloat16(f - __bfloat162float(h));
}

__device__ __forceinline__ void mma16816(float* c, const unsigned* a,
                                         unsigned b0, unsigned b1) {
    asm volatile(
        "mma.sync.aligned.m16n8k16.row.col.f32.bf16.bf16.f32 "
        "{%0,%1,%2,%3}, {%4,%5,%6,%7}, {%8,%9}, {%0,%1,%2,%3};"
        : "+f"(c[0]), "+f"(c[1]), "+f"(c[2]), "+f"(c[3])
        : "r"(a[0]), "r"(a[1]), "r"(a[2]), "r"(a[3]), "r"(b0), "r"(b1));
}

// ---------------------------------------------------------------------------
// Kernel 1: mask branch. 8 channels per round; per-thread offsets precomputed.
// ---------------------------------------------------------------------------
__global__ void mask_kernel2(const float* __restrict__ mask,
                             const float* __restrict__ dw_w,
                             const float* __restrict__ dw_b,
                             const float* __restrict__ pw_w,
                             const float* __restrict__ pw_b) {
    __shared__ float tilef[8 * 360];   // cc*360 + hy*20 + wx
    __shared__ float sdw[Cc][9];
    __shared__ float sdb[Cc];
    __shared__ float swbar[Cc + 1];
    __shared__ float wpart[4][Cc];

    int bp = blockIdx.z;
    int h0 = blockIdx.y * 16, w0 = blockIdx.x * 16;
    int tx = threadIdx.x, ty = threadIdx.y;
    int tid = ty * 16 + tx;

    for (int i = tid; i < Cc * 9; i += 256) sdw[i / 9][i % 9] = dw_w[i];
    for (int i = tid; i < Cc; i += 256) sdb[i] = dw_b[i];
    {
        int c = tid & 63, dg = tid >> 6;
        float s = 0.f;
        for (int d = dg * 16; d < dg * 16 + 16; ++d) s += pw_w[d * Cc + c];
        wpart[dg][c] = s;
    }
    if (tid >= 192) {
        float s = pw_b[tid - 192];
#pragma unroll
        for (int o = 16; o > 0; o >>= 1)
            s += __shfl_down_sync(0xFFFFFFFFu, s, o);
        if (tid == 192) swbar[Cc] = s * (1.0f / Cc);
    }

    // precompute per-thread load slots (invariant across channel rounds)
    int off_[11];
    int dst_[11];
    unsigned valid = 0;
    int nslots = 0;
#pragma unroll
    for (int s = 0; s < 11; ++s) {
        int i = tid + s * 256;
        if (i < 2592) {
            int cc = i / 324, r = i % 324;
            int hy = r / 18, wx = r % 18;
            int gh = h0 + hy - 1, gw = w0 + wx - 1;
            bool ok = (gh >= 0 && gh < Hh && gw >= 0 && gw < Wd);
            off_[s] = cc * HW + gh * Wd + gw;
            dst_[s] = cc * 360 + hy * 20 + wx;
            if (ok) valid |= (1u << s);
            nslots = s + 1;
        }
    }

    __syncthreads();
    if (tid < Cc)
        swbar[tid] = (wpart[0][tid] + wpart[1][tid] + wpart[2][tid] + wpart[3][tid]) * (1.0f / Cc);

    float acc = 0.f;
    const float* base = mask + (size_t)bp * Cc * HW;

    for (int cb = 0; cb < Cc; cb += 8) {
        __syncthreads();
        const float* bb = base + (size_t)cb * HW;
#pragma unroll
        for (int s = 0; s < 11; ++s) {
            if (s < nslots) {
                float v = ((valid >> s) & 1u) ? bb[off_[s]] : 0.f;
                tilef[dst_[s]] = v;
            }
        }
        __syncthreads();
#pragma unroll
        for (int cc = 0; cc < 8; ++cc) {
            int c = cb + cc;
            const float* tt = tilef + cc * 360 + ty * 20 + tx;
            float y = sdb[c];
#pragma unroll
            for (int dy = 0; dy < 3; ++dy)
#pragma unroll
                for (int dx = 0; dx < 3; ++dx)
                    y += tt[dy * 20 + dx] * sdw[c][dy * 3 + dx];
            float g = 0.5f * y * (1.0f + erff(y * 0.70710678118654752f));
            acc += swbar[c] * g;
        }
    }
    acc += swbar[Cc];
    g_mb[(size_t)bp * HW + (h0 + ty) * Wd + (w0 + tx)] = acc;
}

// ---------------------------------------------------------------------------
// Kernel 2: FULLY FUSED per-32-token tile, 3 GEMM phases (per-head V kept):
//   QK GEMM (N=128) -> Cf -> att (regs) -> V GEMM (N=64) -> Cf
//   -> o = att*v (per-head, in-place into A) -> P GEMM (N=64) -> +bias -> out
// smem (bf16 elems unless noted):
//   aHi[128*72] @0, aLo @9216          x tile, later o tile (hi/lo)
//   bHi[128*72] @18432, bLo @27648     [wq;wk] -> wv -> wp
//   Cf  fp32[128*132] @36864 elems     QK result / V result / out staging
//   mb_s[128] sb[64] sr[8] fp32 after Cf
// total = 142112 B -> 1 CTA/SM
// ---------------------------------------------------------------------------
#define ATTN_SMEM_BYTES 142112

__global__ void __launch_bounds__(256, 1)
attn_fused(const float* __restrict__ x_in,
           const float* __restrict__ wq,
           const float* __restrict__ wk,
           const float* __restrict__ wv,
           const float* __restrict__ wp,
           const float* __restrict__ b_proj,
           const float* __restrict__ rescale,
           float* __restrict__ out) {
    extern __shared__ __nv_bfloat16 smb[];
    __nv_bfloat16* aHi = smb;
    __nv_bfloat16* aLo = smb + 9216;
    __nv_bfloat16* bHi = smb + 18432;
    __nv_bfloat16* bLo = smb + 27648;
    float* Cf    = (float*)(smb + 36864);
    float* mb_s  = Cf + 16896;
    float* sb    = mb_s + 128;
    float* sr    = sb + 64;
    float* out_s = Cf;   // overlay for final staging

    int tid = threadIdx.x;
    int b = blockIdx.y;
    int pos0 = blockIdx.x * 32;

    // stage B = [wq;wk]
    for (int i = tid; i < 8192; i += 256) {
        int n = i >> 6, c = i & 63;
        float w = (n < 64) ? wq[n * 64 + c] : wk[(n - 64) * 64 + c];
        __nv_bfloat16 h, l;
        bsplit(w, h, l);
        bHi[n * 72 + c] = h;
        bLo[n * 72 + c] = l;
    }
    // stage A: x tile; rows = t*4+p
    for (int i4 = tid; i4 < 2048; i4 += 256) {
        int pc = i4 >> 3;
        int t4 = (i4 & 7) * 4;
        int p = pc >> 6, c = pc & 63;
        float4 xv = *(const float4*)(x_in + (size_t)((b * 4 + p) * 64 + c) * HW + pos0 + t4);
        float xs[4] = {xv.x, xv.y, xv.z, xv.w};
#pragma unroll
        for (int j = 0; j < 4; ++j) {
            int row = (t4 + j) * 4 + p;
            __nv_bfloat16 h, l;
            bsplit(xs[j], h, l);
            aHi[row * 72 + c] = h;
            aLo[row * 72 + c] = l;
        }
    }
    if (tid < 128) {
        int p = tid >> 5, t = tid & 31;
        mb_s[t * 4 + p] = g_mb[(size_t)(b * 4 + p) * HW + pos0 + t];
    }
    if (tid < 64) sb[tid] = b_proj[tid];
    if (tid < 8) sr[tid] = rescale[tid];
    __syncthreads();

    int lane = tid & 31, wid = tid >> 5;
    int gid = lane >> 2, tig = lane & 3;
    const int t = tid >> 3, h = tid & 7;

    // ===== phase 1: QK GEMM, N=128 =====
    {
        int wm = wid & 3, wn = wid >> 2;
        int row0 = wm * 32, col0 = wn * 64;

        float acc[2][8][4];
#pragma unroll
        for (int mt = 0; mt < 2; ++mt)
#pragma unroll
            for (int nb = 0; nb < 8; ++nb)
#pragma unroll
                for (int i = 0; i < 4; ++i) acc[mt][nb][i] = 0.f;

#pragma unroll
        for (int kk = 0; kk < 4; ++kk) {
            unsigned aH[2][4], aL[2][4];
#pragma unroll
            for (int mt = 0; mt < 2; ++mt) {
                const __nv_bfloat16* ab = aHi + (row0 + mt * 16 + gid) * 72 + kk * 16 + 2 * tig;
                aH[mt][0] = *(const unsigned*)(ab);
                aH[mt][1] = *(const unsigned*)(ab + 8 * 72);
                aH[mt][2] = *(const unsigned*)(ab + 8);
                aH[mt][3] = *(const unsigned*)(ab + 8 * 72 + 8);
                const __nv_bfloat16* al = aLo + (row0 + mt * 16 + gid) * 72 + kk * 16 + 2 * tig;
                aL[mt][0] = *(const unsigned*)(al);
                aL[mt][1] = *(const unsigned*)(al + 8 * 72);
                aL[mt][2] = *(const unsigned*)(al + 8);
                aL[mt][3] = *(const unsigned*)(al + 8 * 72 + 8);
            }
#pragma unroll
            for (int nb = 0; nb < 8; ++nb) {
                int n = col0 + nb * 8 + gid;
                const __nv_bfloat16* bh = bHi + n * 72 + kk * 16 + 2 * tig;
                unsigned bh0 = *(const unsigned*)(bh);
                unsigned bh1 = *(const unsigned*)(bh + 8);
                const __nv_bfloat16* bl = bLo + n * 72 + kk * 16 + 2 * tig;
                unsigned bl0 = *(const unsigned*)(bl);
                unsigned bl1 = *(const unsigned*)(bl + 8);
#pragma unroll
                for (int mt = 0; mt < 2; ++mt) {
                    mma16816(acc[mt][nb], aH[mt], bh0, bh1);
                    mma16816(acc[mt][nb], aH[mt], bl0, bl1);
                    mma16816(acc[mt][nb], aL[mt], bh0, bh1);
                }
            }
        }
#pragma unroll
        for (int mt = 0; mt < 2; ++mt)
#pragma unroll
            for (int nb = 0; nb < 8; ++nb) {
                int row = row0 + mt * 16 + gid;
                int col = col0 + nb * 8 + 2 * tig;
                float* dst = Cf + row * 132 + col;
                *(float2*)dst = make_float2(acc[mt][nb][0], acc[mt][nb][1]);
                *(float2*)(dst + 8 * 132) = make_float2(acc[mt][nb][2], acc[mt][nb][3]);
            }
    }
    __syncthreads();

    // ===== midsection 1: normalize + softmax -> att in registers =====
    float att[4][4];
    {
        float q[4][8], k[4][8];
#pragma unroll
        for (int p = 0; p < 4; ++p) {
            const float* cr = Cf + (t * 4 + p) * 132 + h * 8;
#pragma unroll
            for (int j2 = 0; j2 < 4; ++j2) {
                float2 qq = *(const float2*)(cr + 2 * j2);
                q[p][2 * j2] = qq.x; q[p][2 * j2 + 1] = qq.y;
                float2 kk2 = *(const float2*)(cr + 64 + 2 * j2);
                k[p][2 * j2] = kk2.x; k[p][2 * j2 + 1] = kk2.y;
            }
        }
#pragma unroll
        for (int p = 0; p < 4; ++p) {
            float sq = 0.f, sk = 0.f;
#pragma unroll
            for (int j = 0; j < 8; ++j) { sq += q[p][j] * q[p][j]; sk += k[p][j] * k[p][j]; }
            float iq = 1.0f / fmaxf(sqrtf(sq), 1e-12f);
            float ik = 1.0f / fmaxf(sqrtf(sk), 1e-12f);
#pragma unroll
            for (int j = 0; j < 8; ++j) { q[p][j] *= iq; k[p][j] *= ik; }
        }
        float rh = sr[h];
        float mbl[4];
#pragma unroll
        for (int p = 0; p < 4; ++p) mbl[p] = mb_s[t * 4 + p];
#pragma unroll
        for (int p = 0; p < 4; ++p) {
#pragma unroll
            for (int pq = 0; pq < 4; ++pq) {
                float d = 0.f;
#pragma unroll
                for (int j = 0; j < 8; ++j) d += q[p][j] * k[pq][j];
                att[p][pq] = d * rh + (mbl[pq] - mbl[p]);
            }
            float mx = fmaxf(fmaxf(att[p][0], att[p][1]), fmaxf(att[p][2], att[p][3]));
            float s = 0.f;
#pragma unroll
            for (int pq = 0; pq < 4; ++pq) { att[p][pq] = __expf(att[p][pq] - mx); s += att[p][pq]; }
            float inv = 1.0f / s;
#pragma unroll
            for (int pq = 0; pq < 4; ++pq) att[p][pq] *= inv;
        }
    }
    // restage B = wv (all threads must be past Cf q/k reads and QK B reads)
    __syncthreads();
    for (int i = tid; i < 4096; i += 256) {
        int n = i >> 6, c = i & 63;
        __nv_bfloat16 hh, ll;
        bsplit(wv[i], hh, ll);
        bHi[n * 72 + c] = hh;
        bLo[n * 72 + c] = ll;
    }
    __syncthreads();

    // ===== phase 2: V GEMM, N=64, A=x -> Cf =====
    {
        int wm = wid & 3, wn = wid >> 2;
        int row0 = wm * 32, col0 = wn * 32;

        float acc[2][4][4];
#pragma unroll
        for (int mt = 0; mt < 2; ++mt)
#pragma unroll
            for (int nb = 0; nb < 4; ++nb)
#pragma unroll
                for (int i = 0; i < 4; ++i) acc[mt][nb][i] = 0.f;

#pragma unroll
        for (int kk = 0; kk < 4; ++kk) {
            unsigned aH[2][4], aL[2][4];
#pragma unroll
            for (int mt = 0; mt < 2; ++mt) {
                const __nv_bfloat16* ab = aHi + (row0 + mt * 16 + gid) * 72 + kk * 16 + 2 * tig;
                aH[mt][0] = *(const unsigned*)(ab);
                aH[mt][1] = *(const unsigned*)(ab + 8 * 72);
                aH[mt][2] = *(const unsigned*)(ab + 8);
                aH[mt][3] = *(const unsigned*)(ab + 8 * 72 + 8);
                const __nv_bfloat16* al = aLo + (row0 + mt * 16 + gid) * 72 + kk * 16 + 2 * tig;
                aL[mt][0] = *(const unsigned*)(al);
                aL[mt][1] = *(const unsigned*)(al + 8 * 72);
                aL[mt][2] = *(const unsigned*)(al + 8);
                aL[mt][3] = *(const unsigned*)(al + 8 * 72 + 8);
            }
#pragma unroll
            for (int nb = 0; nb < 4; ++nb) {
                int n = col0 + nb * 8 + gid;
                const __nv_bfloat16* bh = bHi + n * 72 + kk * 16 + 2 * tig;
                unsigned bh0 = *(const unsigned*)(bh);
                unsigned bh1 = *(const unsigned*)(bh + 8);
                const __nv_bfloat16* bl = bLo + n * 72 + kk * 16 + 2 * tig;
                unsigned bl0 = *(const unsigned*)(bl);
                unsigned bl1 = *(const unsigned*)(bl + 8);
#pragma unroll
                for (int mt = 0; mt < 2; ++mt) {
                    mma16816(acc[mt][nb], aH[mt], bh0, bh1);
                    mma16816(acc[mt][nb], aH[mt], bl0, bl1);
                    mma16816(acc[mt][nb], aL[mt], bh0, bh1);
                }
            }
        }
#pragma unroll
        for (int mt = 0; mt < 2; ++mt)
#pragma unroll
            for (int nb = 0; nb < 4; ++nb) {
                int row = row0 + mt * 16 + gid;
                int col = col0 + nb * 8 + 2 * tig;
                float* dst = Cf + row * 132 + col;
                *(float2*)dst = make_float2(acc[mt][nb][0], acc[mt][nb][1]);
                *(float2*)(dst + 8 * 132) = make_float2(acc[mt][nb][2], acc[mt][nb][3]);
            }
    }
    __syncthreads();

    // ===== midsection 2: o = att*v (per head) -> A ; restage B = wp =====
    {
#pragma unroll
        for (int j = 0; j < 8; ++j) {
            int c = h * 8 + j;
            float vv[4];
#pragma unroll
            for (int p = 0; p < 4; ++p) vv[p] = Cf[(t * 4 + p) * 132 + c];
#pragma unroll
            for (int p = 0; p < 4; ++p) {
                float o = att[p][0] * vv[0] + att[p][1] * vv[1] +
                          att[p][2] * vv[2] + att[p][3] * vv[3];
                __nv_bfloat16 hh, ll;
                bsplit(o, hh, ll);
                int row = t * 4 + p;
                aHi[row * 72 + c] = hh;
                aLo[row * 72 + c] = ll;
            }
        }
    }
    for (int i = tid; i < 4096; i += 256) {
        int n = i >> 6, c = i & 63;
        __nv_bfloat16 hh, ll;
        bsplit(wp[i], hh, ll);
        bHi[n * 72 + c] = hh;
        bLo[n * 72 + c] = ll;
    }
    __syncthreads();

    // ===== phase 3: out = o @ wp^T, N=64 =====
    {
        int wm = wid & 3, wn = wid >> 2;
        int row0 = wm * 32, col0 = wn * 32;

        float acc[2][4][4];
#pragma unroll
        for (int mt = 0; mt < 2; ++mt)
#pragma unroll
            for (int nb = 0; nb < 4; ++nb)
#pragma unroll
                for (int i = 0; i < 4; ++i) acc[mt][nb][i] = 0.f;

#pragma unroll
        for (int kk = 0; kk < 4; ++kk) {
            unsigned aH[2][4], aL[2][4];
#pragma unroll
            for (int mt = 0; mt < 2; ++mt) {
                const __nv_bfloat16* ab = aHi + (row0 + mt * 16 + gid) * 72 + kk * 16 + 2 * tig;
                aH[mt][0] = *(const unsigned*)(ab);
                aH[mt][1] = *(const unsigned*)(ab + 8 * 72);
                aH[mt][2] = *(const unsigned*)(ab + 8);
                aH[mt][3] = *(const unsigned*)(ab + 8 * 72 + 8);
                const __nv_bfloat16* al = aLo + (row0 + mt * 16 + gid) * 72 + kk * 16 + 2 * tig;
                aL[mt][0] = *(const unsigned*)(al);
                aL[mt][1] = *(const unsigned*)(al + 8 * 72);
                aL[mt][2] = *(const unsigned*)(al + 8);
                aL[mt][3] = *(const unsigned*)(al + 8 * 72 + 8);
            }
#pragma unroll
            for (int nb = 0; nb < 4; ++nb) {
                int n = col0 + nb * 8 + gid;
                const __nv_bfloat16* bh = bHi + n * 72 + kk * 16 + 2 * tig;
                unsigned bh0 = *(const unsigned*)(bh);
                unsigned bh1 = *(const unsigned*)(bh + 8);
                const __nv_bfloat16* bl = bLo + n * 72 + kk * 16 + 2 * tig;
                unsigned bl0 = *(const unsigned*)(bl);
                unsigned bl1 = *(const unsigned*)(bl + 8);
#pragma unroll
                for (int mt = 0; mt < 2; ++mt) {
                    mma16816(acc[mt][nb], aH[mt], bh0, bh1);
                    mma16816(acc[mt][nb], aH[mt], bl0, bl1);
                    mma16816(acc[mt][nb], aL[mt], bh0, bh1);
                }
            }
        }
        __syncthreads();   // Cf (v) dead; becomes out_s
#pragma unroll
        for (int mt = 0; mt < 2; ++mt)
#pragma unroll
            for (int nb = 0; nb < 4; ++nb) {
                int row = row0 + mt * 16 + gid;
                int col = col0 + nb * 8 + 2 * tig;
                int tt = row >> 2, p = row & 3;
                out_s[(p * 64 + col) * 32 + tt]         = acc[mt][nb][0] + sb[col];
                out_s[(p * 64 + col + 1) * 32 + tt]     = acc[mt][nb][1] + sb[col + 1];
                out_s[(p * 64 + col) * 32 + tt + 2]     = acc[mt][nb][2] + sb[col];
                out_s[(p * 64 + col + 1) * 32 + tt + 2] = acc[mt][nb][3] + sb[col + 1];
            }
    }
    __syncthreads();

    // coalesced writeback
    for (int i4 = tid; i4 < 2048; i4 += 256) {
        int pc = i4 >> 3;
        int t4 = (i4 & 7) * 4;
        int p = pc >> 6, c = pc & 63;
        float4 vv = *(const float4*)(out_s + pc * 32 + t4);
        *(float4*)(out + (size_t)((b * 4 + p) * 64 + c) * HW + pos0 + t4) = vv;
    }
}

// ---------------------------------------------------------------------------
extern "C" void kernel_launch(void* const* d_in, const int* in_sizes, int n_in,
                              void* d_out, int out_size) {
    (void)in_sizes; (void)n_in; (void)out_size;
    const float* x_in   = (const float*)d_in[0];
    const float* mask   = (const float*)d_in[1];
    const float* wq     = (const float*)d_in[2];
    const float* wk     = (const float*)d_in[3];
    const float* wv     = (const float*)d_in[4];
    const float* w_proj = (const float*)d_in[5];
    const float* b_proj = (const float*)d_in[6];
    const float* rescale= (const float*)d_in[7];
    const float* dw_w   = (const float*)d_in[8];
    const float* dw_b   = (const float*)d_in[9];
    const float* pw_w   = (const float*)d_in[10];
    const float* pw_b   = (const float*)d_in[11];
    float* out = (float*)d_out;

    cudaFuncSetAttribute(attn_fused, cudaFuncAttributeMaxDynamicSharedMemorySize,
                         ATTN_SMEM_BYTES);

    mask_kernel2<<<dim3(8, 8, 16), dim3(16, 16)>>>(mask, dw_w, dw_b, pw_w, pw_b);
    attn_fused<<<dim3(512, Bn), 256, ATTN_SMEM_BYTES>>>(
        x_in, wq, wk, wv, w_proj, b_proj, rescale, out);
}

// round 10
// speedup vs baseline: 1.2214x; 1.2214x over previous
#include <cuda_runtime.h>
#include <cuda_bf16.h>
#include <math.h>

#define Bn 4
#define Pp 4
#define Cc 64
#define NH 8
#define Hh 128
#define Wd 128
#define HW 16384

// scratch (no cudaMalloc allowed)
__device__ float g_mb[16 * HW];   // mask bias per (b,p,pos)

// ---------------------------------------------------------------------------
// helpers
// ---------------------------------------------------------------------------
__device__ __forceinline__ void bsplit(float f, __nv_bfloat16& h, __nv_bfloat16& l) {
    h = __float2bfloat16(f);
    l = __float2bfloat16(f - __bfloat162float(h));
}

__device__ __forceinline__ void mma16816(float* c, const unsigned* a,
                                         unsigned b0, unsigned b1) {
    asm volatile(
        "mma.sync.aligned.m16n8k16.row.col.f32.bf16.bf16.f32 "
        "{%0,%1,%2,%3}, {%4,%5,%6,%7}, {%8,%9}, {%0,%1,%2,%3};"
        : "+f"(c[0]), "+f"(c[1]), "+f"(c[2]), "+f"(c[3])
        : "r"(a[0]), "r"(a[1]), "r"(a[2]), "r"(a[3]), "r"(b0), "r"(b1));
}

// ---------------------------------------------------------------------------
// Kernel 1: mask branch. 8 channels per round; per-thread offsets precomputed.
// ---------------------------------------------------------------------------
__global__ void mask_kernel2(const float* __restrict__ mask,
                             const float* __restrict__ dw_w,
                             const float* __restrict__ dw_b,
                             const float* __restrict__ pw_w,
                             const float* __restrict__ pw_b) {
    __shared__ float tilef[8 * 360];   // cc*360 + hy*20 + wx
    __shared__ float sdw[Cc][9];
    __shared__ float sdb[Cc];
    __shared__ float swbar[Cc + 1];
    __shared__ float wpart[4][Cc];

    int bp = blockIdx.z;
    int h0 = blockIdx.y * 16, w0 = blockIdx.x * 16;
    int tx = threadIdx.x, ty = threadIdx.y;
    int tid = ty * 16 + tx;

    for (int i = tid; i < Cc * 9; i += 256) sdw[i / 9][i % 9] = dw_w[i];
    for (int i = tid; i < Cc; i += 256) sdb[i] = dw_b[i];
    {
        int c = tid & 63, dg = tid >> 6;
        float s = 0.f;
        for (int d = dg * 16; d < dg * 16 + 16; ++d) s += pw_w[d * Cc + c];
        wpart[dg][c] = s;
    }
    if (tid >= 192) {
        float s = pw_b[tid - 192];
#pragma unroll
        for (int o = 16; o > 0; o >>= 1)
            s += __shfl_down_sync(0xFFFFFFFFu, s, o);
        if (tid == 192) swbar[Cc] = s * (1.0f / Cc);
    }

    int off_[11];
    int dst_[11];
    unsigned valid = 0;
    int nslots = 0;
#pragma unroll
    for (int s = 0; s < 11; ++s) {
        int i = tid + s * 256;
        if (i < 2592) {
            int cc = i / 324, r = i % 324;
            int hy = r / 18, wx = r % 18;
            int gh = h0 + hy - 1, gw = w0 + wx - 1;
            bool ok = (gh >= 0 && gh < Hh && gw >= 0 && gw < Wd);
            off_[s] = cc * HW + gh * Wd + gw;
            dst_[s] = cc * 360 + hy * 20 + wx;
            if (ok) valid |= (1u << s);
            nslots = s + 1;
        }
    }

    __syncthreads();
    if (tid < Cc)
        swbar[tid] = (wpart[0][tid] + wpart[1][tid] + wpart[2][tid] + wpart[3][tid]) * (1.0f / Cc);

    float acc = 0.f;
    const float* base = mask + (size_t)bp * Cc * HW;

    for (int cb = 0; cb < Cc; cb += 8) {
        __syncthreads();
        const float* bb = base + (size_t)cb * HW;
#pragma unroll
        for (int s = 0; s < 11; ++s) {
            if (s < nslots) {
                float v = ((valid >> s) & 1u) ? bb[off_[s]] : 0.f;
                tilef[dst_[s]] = v;
            }
        }
        __syncthreads();
#pragma unroll
        for (int cc = 0; cc < 8; ++cc) {
            int c = cb + cc;
            const float* tt = tilef + cc * 360 + ty * 20 + tx;
            float y = sdb[c];
#pragma unroll
            for (int dy = 0; dy < 3; ++dy)
#pragma unroll
                for (int dx = 0; dx < 3; ++dx)
                    y += tt[dy * 20 + dx] * sdw[c][dy * 3 + dx];
            float g = 0.5f * y * (1.0f + erff(y * 0.70710678118654752f));
            acc += swbar[c] * g;
        }
    }
    acc += swbar[Cc];
    g_mb[(size_t)bp * HW + (h0 + ty) * Wd + (w0 + tx)] = acc;
}

// ---------------------------------------------------------------------------
// Kernel 2: fused per-32-token tile, now 4 GEMM phases all N=64 so smem fits
// 2 CTAs/SM (barrier overlap across CTAs):
//   Q GEMM -> q regs -> K GEMM -> att regs -> V GEMM -> o=att*v -> P GEMM
// smem (bf16 elem offsets):
//   aHi @0 (128x72), aLo @9216            x tile, later o tile
//   bHi @18432 (64x72), bLo @23040        wq -> wk -> wv -> wp
//   Cf fp32 @byte 55296, 128x68 = 34816B  per-phase C / out staging
//   mb_s[128] sb[64] sr[8] after Cf
// total = 90912 B -> 2 CTAs/SM
// ---------------------------------------------------------------------------
#define ATTN_SMEM_BYTES 90912

__global__ void __launch_bounds__(256, 2)
attn_fused(const float* __restrict__ x_in,
           const float* __restrict__ wq,
           const float* __restrict__ wk,
           const float* __restrict__ wv,
           const float* __restrict__ wp,
           const float* __restrict__ b_proj,
           const float* __restrict__ rescale,
           float* __restrict__ out) {
    extern __shared__ __nv_bfloat16 smb[];
    __nv_bfloat16* aHi = smb;
    __nv_bfloat16* aLo = smb + 9216;
    __nv_bfloat16* bHi = smb + 18432;
    __nv_bfloat16* bLo = smb + 23040;
    float* Cf    = (float*)(smb + 27648);
    float* mb_s  = Cf + 8704;
    float* sb    = mb_s + 128;
    float* sr    = sb + 64;
    float* out_s = Cf;

    int tid = threadIdx.x;
    int b = blockIdx.y;
    int pos0 = blockIdx.x * 32;

    // stage B = wq
    for (int i = tid; i < 4096; i += 256) {
        int n = i >> 6, c = i & 63;
        __nv_bfloat16 hh, ll;
        bsplit(wq[i], hh, ll);
        bHi[n * 72 + c] = hh;
        bLo[n * 72 + c] = ll;
    }
    // stage A: x tile; rows = t*4+p
    for (int i4 = tid; i4 < 2048; i4 += 256) {
        int pc = i4 >> 3;
        int t4 = (i4 & 7) * 4;
        int p = pc >> 6, c = pc & 63;
        float4 xv = *(const float4*)(x_in + (size_t)((b * 4 + p) * 64 + c) * HW + pos0 + t4);
        float xs[4] = {xv.x, xv.y, xv.z, xv.w};
#pragma unroll
        for (int j = 0; j < 4; ++j) {
            int row = (t4 + j) * 4 + p;
            __nv_bfloat16 hh, ll;
            bsplit(xs[j], hh, ll);
            aHi[row * 72 + c] = hh;
            aLo[row * 72 + c] = ll;
        }
    }
    if (tid < 128) {
        int p = tid >> 5, t = tid & 31;
        mb_s[t * 4 + p] = g_mb[(size_t)(b * 4 + p) * HW + pos0 + t];
    }
    if (tid < 64) sb[tid] = b_proj[tid];
    if (tid < 8) sr[tid] = rescale[tid];
    __syncthreads();

    int lane = tid & 31, wid = tid >> 5;
    int gid = lane >> 2, tig = lane & 3;
    const int t = tid >> 3, h = tid & 7;
    int wm = wid & 3, wn = wid >> 2;
    int row0 = wm * 32, col0 = wn * 32;

    // ---- N=64 GEMM macro body (A = aHi/aLo, B = bHi/bLo, C -> Cf[row*68+col])
#define GEMM64(EPILOG)                                                          \
    {                                                                           \
        float acc[2][4][4];                                                     \
        _Pragma("unroll")                                                       \
        for (int mt = 0; mt < 2; ++mt)                                          \
            _Pragma("unroll")                                                   \
            for (int nb = 0; nb < 4; ++nb)                                      \
                _Pragma("unroll")                                               \
                for (int i = 0; i < 4; ++i) acc[mt][nb][i] = 0.f;               \
        _Pragma("unroll")                                                       \
        for (int kk = 0; kk < 4; ++kk) {                                        \
            unsigned aH[2][4], aL[2][4];                                        \
            _Pragma("unroll")                                                   \
            for (int mt = 0; mt < 2; ++mt) {                                    \
                const __nv_bfloat16* ab = aHi + (row0 + mt * 16 + gid) * 72 + kk * 16 + 2 * tig; \
                aH[mt][0] = *(const unsigned*)(ab);                             \
                aH[mt][1] = *(const unsigned*)(ab + 8 * 72);                    \
                aH[mt][2] = *(const unsigned*)(ab + 8);                         \
                aH[mt][3] = *(const unsigned*)(ab + 8 * 72 + 8);                \
                const __nv_bfloat16* al = aLo + (row0 + mt * 16 + gid) * 72 + kk * 16 + 2 * tig; \
                aL[mt][0] = *(const unsigned*)(al);                             \
                aL[mt][1] = *(const unsigned*)(al + 8 * 72);                    \
                aL[mt][2] = *(const unsigned*)(al + 8);                         \
                aL[mt][3] = *(const unsigned*)(al + 8 * 72 + 8);                \
            }                                                                   \
            _Pragma("unroll")                                                   \
            for (int nb = 0; nb < 4; ++nb) {                                    \
                int n = col0 + nb * 8 + gid;                                    \
                const __nv_bfloat16* bh = bHi + n * 72 + kk * 16 + 2 * tig;     \
                unsigned bh0 = *(const unsigned*)(bh);                          \
                unsigned bh1 = *(const unsigned*)(bh + 8);                      \
                const __nv_bfloat16* bl = bLo + n * 72 + kk * 16 + 2 * tig;     \
                unsigned bl0 = *(const unsigned*)(bl);                          \
                unsigned bl1 = *(const unsigned*)(bl + 8);                      \
                _Pragma("unroll")                                               \
                for (int mt = 0; mt < 2; ++mt) {                                \
                    mma16816(acc[mt][nb], aH[mt], bh0, bh1);                    \
                    mma16816(acc[mt][nb], aH[mt], bl0, bl1);                    \
                    mma16816(acc[mt][nb], aL[mt], bh0, bh1);                    \
                }                                                               \
            }                                                                   \
        }                                                                       \
        EPILOG                                                                  \
    }

#define EPI_CF                                                                  \
        _Pragma("unroll")                                                       \
        for (int mt = 0; mt < 2; ++mt)                                          \
            _Pragma("unroll")                                                   \
            for (int nb = 0; nb < 4; ++nb) {                                    \
                int row = row0 + mt * 16 + gid;                                 \
                int col = col0 + nb * 8 + 2 * tig;                              \
                float* dst = Cf + row * 68 + col;                               \
                *(float2*)dst = make_float2(acc[mt][nb][0], acc[mt][nb][1]);    \
                *(float2*)(dst + 8 * 68) = make_float2(acc[mt][nb][2], acc[mt][nb][3]); \
            }

    // ===== phase 1: Q GEMM =====
    GEMM64(EPI_CF)
    __syncthreads();

    // read q -> regs; stage B = wk
    float q[4][8];
#pragma unroll
    for (int p = 0; p < 4; ++p) {
        const float* cr = Cf + (t * 4 + p) * 68 + h * 8;
#pragma unroll
        for (int j2 = 0; j2 < 4; ++j2) {
            float2 qq = *(const float2*)(cr + 2 * j2);
            q[p][2 * j2] = qq.x; q[p][2 * j2 + 1] = qq.y;
        }
    }
    for (int i = tid; i < 4096; i += 256) {
        int n = i >> 6, c = i & 63;
        __nv_bfloat16 hh, ll;
        bsplit(wk[i], hh, ll);
        bHi[n * 72 + c] = hh;
        bLo[n * 72 + c] = ll;
    }
    __syncthreads();

    // ===== phase 2: K GEMM =====
    GEMM64(EPI_CF)
    __syncthreads();

    // read k; normalize; softmax -> att; stage B = wv
    float att[4][4];
    {
        float k[4][8];
#pragma unroll
        for (int p = 0; p < 4; ++p) {
            const float* cr = Cf + (t * 4 + p) * 68 + h * 8;
#pragma unroll
            for (int j2 = 0; j2 < 4; ++j2) {
                float2 kk2 = *(const float2*)(cr + 2 * j2);
                k[p][2 * j2] = kk2.x; k[p][2 * j2 + 1] = kk2.y;
            }
        }
#pragma unroll
        for (int p = 0; p < 4; ++p) {
            float sq = 0.f, sk = 0.f;
#pragma unroll
            for (int j = 0; j < 8; ++j) { sq += q[p][j] * q[p][j]; sk += k[p][j] * k[p][j]; }
            float iq = 1.0f / fmaxf(sqrtf(sq), 1e-12f);
            float ik = 1.0f / fmaxf(sqrtf(sk), 1e-12f);
#pragma unroll
            for (int j = 0; j < 8; ++j) { q[p][j] *= iq; k[p][j] *= ik; }
        }
        float rh = sr[h];
        float mbl[4];
#pragma unroll
        for (int p = 0; p < 4; ++p) mbl[p] = mb_s[t * 4 + p];
#pragma unroll
        for (int p = 0; p < 4; ++p) {
#pragma unroll
            for (int pq = 0; pq < 4; ++pq) {
                float d = 0.f;
#pragma unroll
                for (int j = 0; j < 8; ++j) d += q[p][j] * k[pq][j];
                att[p][pq] = d * rh + (mbl[pq] - mbl[p]);
            }
            float mx = fmaxf(fmaxf(att[p][0], att[p][1]), fmaxf(att[p][2], att[p][3]));
            float s = 0.f;
#pragma unroll
            for (int pq = 0; pq < 4; ++pq) { att[p][pq] = __expf(att[p][pq] - mx); s += att[p][pq]; }
            float inv = 1.0f / s;
#pragma unroll
            for (int pq = 0; pq < 4; ++pq) att[p][pq] *= inv;
        }
    }
    for (int i = tid; i < 4096; i += 256) {
        int n = i >> 6, c = i & 63;
        __nv_bfloat16 hh, ll;
        bsplit(wv[i], hh, ll);
        bHi[n * 72 + c] = hh;
        bLo[n * 72 + c] = ll;
    }
    __syncthreads();

    // ===== phase 3: V GEMM =====
    GEMM64(EPI_CF)
    __syncthreads();

    // o = att*v -> A (exclusive slots); stage B = wp
    {
#pragma unroll
        for (int j = 0; j < 8; ++j) {
            int c = h * 8 + j;
            float vv[4];
#pragma unroll
            for (int p = 0; p < 4; ++p) vv[p] = Cf[(t * 4 + p) * 68 + c];
#pragma unroll
            for (int p = 0; p < 4; ++p) {
                float o = att[p][0] * vv[0] + att[p][1] * vv[1] +
                          att[p][2] * vv[2] + att[p][3] * vv[3];
                __nv_bfloat16 hh, ll;
                bsplit(o, hh, ll);
                int row = t * 4 + p;
                aHi[row * 72 + c] = hh;
                aLo[row * 72 + c] = ll;
            }
        }
    }
    for (int i = tid; i < 4096; i += 256) {
        int n = i >> 6, c = i & 63;
        __nv_bfloat16 hh, ll;
        bsplit(wp[i], hh, ll);
        bHi[n * 72 + c] = hh;
        bLo[n * 72 + c] = ll;
    }
    __syncthreads();

    // ===== phase 4: P GEMM -> out staging =====
#define EPI_OUT                                                                 \
        __syncthreads();                                                        \
        _Pragma("unroll")                                                       \
        for (int mt = 0; mt < 2; ++mt)                                          \
            _Pragma("unroll")                                                   \
            for (int nb = 0; nb < 4; ++nb) {                                    \
                int row = row0 + mt * 16 + gid;                                 \
                int col = col0 + nb * 8 + 2 * tig;                              \
                int tt = row >> 2, p = row & 3;                                 \
                out_s[(p * 64 + col) * 32 + tt]         = acc[mt][nb][0] + sb[col]; \
                out_s[(p * 64 + col + 1) * 32 + tt]     = acc[mt][nb][1] + sb[col + 1]; \
                out_s[(p * 64 + col) * 32 + tt + 2]     = acc[mt][nb][2] + sb[col]; \
                out_s[(p * 64 + col + 1) * 32 + tt + 2] = acc[mt][nb][3] + sb[col + 1]; \
            }

    GEMM64(EPI_OUT)
    __syncthreads();

    // coalesced writeback
    for (int i4 = tid; i4 < 2048; i4 += 256) {
        int pc = i4 >> 3;
        int t4 = (i4 & 7) * 4;
        int p = pc >> 6, c = pc & 63;
        float4 vv = *(const float4*)(out_s + pc * 32 + t4);
        *(float4*)(out + (size_t)((b * 4 + p) * 64 + c) * HW + pos0 + t4) = vv;
    }
}

// ---------------------------------------------------------------------------
extern "C" void kernel_launch(void* const* d_in, const int* in_sizes, int n_in,
                              void* d_out, int out_size) {
    (void)in_sizes; (void)n_in; (void)out_size;
    const float* x_in   = (const float*)d_in[0];
    const float* mask   = (const float*)d_in[1];
    const float* wq     = (const float*)d_in[2];
    const float* wk     = (const float*)d_in[3];
    const float* wv     = (const float*)d_in[4];
    const float* w_proj = (const float*)d_in[5];
    const float* b_proj = (const float*)d_in[6];
    const float* rescale= (const float*)d_in[7];
    const float* dw_w   = (const float*)d_in[8];
    const float* dw_b   = (const float*)d_in[9];
    const float* pw_w   = (const float*)d_in[10];
    const float* pw_b   = (const float*)d_in[11];
    float* out = (float*)d_out;

    cudaFuncSetAttribute(attn_fused, cudaFuncAttributeMaxDynamicSharedMemorySize,
                         ATTN_SMEM_BYTES);

    mask_kernel2<<<dim3(8, 8, 16), dim3(16, 16)>>>(mask, dw_w, dw_b, pw_w, pw_b);
    attn_fused<<<dim3(512, Bn), 256, ATTN_SMEM_BYTES>>>(
        x_in, wq, wk, wv, w_proj, b_proj, rescale, out);
}

// round 11
// speedup vs baseline: 1.6370x; 1.3403x over previous
#include <cuda_runtime.h>
#include <cuda_bf16.h>
#include <math.h>

#define Bn 4
#define Pp 4
#define Cc 64
#define NH 8
#define Hh 128
#define Wd 128
#define HW 16384

// scratch (no cudaMalloc allowed)
__device__ float g_mb[16 * HW];   // mask bias per (b,p,pos)

// ---------------------------------------------------------------------------
// helpers
// ---------------------------------------------------------------------------
__device__ __forceinline__ void bsplit(float f, __nv_bfloat16& h, __nv_bfloat16& l) {
    h = __float2bfloat16(f);
    l = __float2bfloat16(f - __bfloat162float(h));
}

__device__ __forceinline__ void mma16816(float* c, const unsigned* a,
                                         unsigned b0, unsigned b1) {
    asm volatile(
        "mma.sync.aligned.m16n8k16.row.col.f32.bf16.bf16.f32 "
        "{%0,%1,%2,%3}, {%4,%5,%6,%7}, {%8,%9}, {%0,%1,%2,%3};"
        : "+f"(c[0]), "+f"(c[1]), "+f"(c[2]), "+f"(c[3])
        : "r"(a[0]), "r"(a[1]), "r"(a[2]), "r"(a[3]), "r"(b0), "r"(b1));
}

// ---------------------------------------------------------------------------
// Kernel 1: mask branch, row-band layout for perfect coalescing.
// Block = 16 rows x 128 cols (one bp); 4 channels per round.
// tile[cc][r][c]: r in 0..17 (gh = h0+r-1), c in 0..129 (gw = c-1),
// cols 0 and 129 are zero (written once).
// ---------------------------------------------------------------------------
#define TS (18 * 132)
__global__ void __launch_bounds__(256)
mask_kernel3(const float* __restrict__ mask,
             const float* __restrict__ dw_w,
             const float* __restrict__ dw_b,
             const float* __restrict__ pw_w,
             const float* __restrict__ pw_b) {
    __shared__ float tilef[4 * TS];
    __shared__ float sdw[Cc][9];
    __shared__ float sdb[Cc];
    __shared__ float swbar[Cc + 1];
    __shared__ float wpart[4][Cc];

    int tid = threadIdx.x;
    int h0 = blockIdx.x * 16;
    int bp = blockIdx.y;

    for (int i = tid; i < Cc * 9; i += 256) sdw[i / 9][i % 9] = dw_w[i];
    for (int i = tid; i < Cc; i += 256) sdb[i] = dw_b[i];
    {
        int c = tid & 63, dg = tid >> 6;
        float s = 0.f;
        for (int d = dg * 16; d < dg * 16 + 16; ++d) s += pw_w[d * Cc + c];
        wpart[dg][c] = s;
    }
    if (tid >= 192 && tid < 224) {
        float s = pw_b[tid - 192] + pw_b[tid - 192 + 32];
#pragma unroll
        for (int o = 16; o > 0; o >>= 1)
            s += __shfl_down_sync(0xFFFFFFFFu, s, o);
        if (tid == 192) swbar[Cc] = s * (1.0f / Cc);
    }
    // zero the side columns once (never overwritten)
    if (tid < 72) {
        int cc = tid / 18, r = tid % 18;
        tilef[cc * TS + r * 132 + 0] = 0.f;
        tilef[cc * TS + r * 132 + 129] = 0.f;
    }
    __syncthreads();
    if (tid < Cc)
        swbar[tid] = (wpart[0][tid] + wpart[1][tid] + wpart[2][tid] + wpart[3][tid]) * (1.0f / Cc);

    const int col = tid & 127;
    const int rowgrp = tid >> 7;          // 0 or 1
    const float* base = mask + (size_t)bp * Cc * HW;

    float acc[8];
#pragma unroll
    for (int j = 0; j < 8; ++j) acc[j] = 0.f;

    for (int cb = 0; cb < Cc; cb += 4) {
        __syncthreads();
        // load 4 channels x 18 rows x 128 cols, fully coalesced 512B rows
#pragma unroll
        for (int it = 0; it < 9; ++it) {
            int r = it * 2 + rowgrp;
            int gh = h0 + r - 1;
            bool ok = (gh >= 0 && gh < Hh);
            const float* src = base + (size_t)cb * HW + gh * Wd + col;
            float* dst = tilef + r * 132 + col + 1;
#pragma unroll
            for (int cc = 0; cc < 4; ++cc)
                dst[cc * TS] = ok ? src[(size_t)cc * HW] : 0.f;
        }
        __syncthreads();
#pragma unroll
        for (int cc = 0; cc < 4; ++cc) {
            int c = cb + cc;
            const float* tb = tilef + cc * TS + col;
            float w0 = sdw[c][0], w1 = sdw[c][1], w2 = sdw[c][2];
            float w3 = sdw[c][3], w4 = sdw[c][4], w5 = sdw[c][5];
            float w6 = sdw[c][6], w7 = sdw[c][7], w8 = sdw[c][8];
            float bias = sdb[c], wb = swbar[c];
#pragma unroll
            for (int j = 0; j < 8; ++j) {
                int lr = rowgrp * 8 + j;
                const float* t0 = tb + lr * 132;
                float y = bias
                    + t0[0] * w0 + t0[1] * w1 + t0[2] * w2
                    + t0[132] * w3 + t0[133] * w4 + t0[134] * w5
                    + t0[264] * w6 + t0[265] * w7 + t0[266] * w8;
                float g = 0.5f * y * (1.0f + erff(y * 0.70710678118654752f));
                acc[j] += wb * g;
            }
        }
    }
    float bb = swbar[Cc];
#pragma unroll
    for (int j = 0; j < 8; ++j) {
        int lr = rowgrp * 8 + j;
        g_mb[(size_t)bp * HW + (h0 + lr) * Wd + col] = acc[j] + bb;
    }
}

// ---------------------------------------------------------------------------
// Kernel 2: fused per-32-token tile (identical to R10 — 248us known-good):
//   Q GEMM -> q regs -> K GEMM -> att regs -> V GEMM -> o=att*v -> P GEMM
// smem total = 90912 B -> 2 CTAs/SM
// ---------------------------------------------------------------------------
#define ATTN_SMEM_BYTES 90912

__global__ void __launch_bounds__(256, 2)
attn_fused(const float* __restrict__ x_in,
           const float* __restrict__ wq,
           const float* __restrict__ wk,
           const float* __restrict__ wv,
           const float* __restrict__ wp,
           const float* __restrict__ b_proj,
           const float* __restrict__ rescale,
           float* __restrict__ out) {
    extern __shared__ __nv_bfloat16 smb[];
    __nv_bfloat16* aHi = smb;
    __nv_bfloat16* aLo = smb + 9216;
    __nv_bfloat16* bHi = smb + 18432;
    __nv_bfloat16* bLo = smb + 23040;
    float* Cf    = (float*)(smb + 27648);
    float* mb_s  = Cf + 8704;
    float* sb    = mb_s + 128;
    float* sr    = sb + 64;
    float* out_s = Cf;

    int tid = threadIdx.x;
    int b = blockIdx.y;
    int pos0 = blockIdx.x * 32;

    // stage B = wq
    for (int i = tid; i < 4096; i += 256) {
        int n = i >> 6, c = i & 63;
        __nv_bfloat16 hh, ll;
        bsplit(wq[i], hh, ll);
        bHi[n * 72 + c] = hh;
        bLo[n * 72 + c] = ll;
    }
    // stage A: x tile; rows = t*4+p
    for (int i4 = tid; i4 < 2048; i4 += 256) {
        int pc = i4 >> 3;
        int t4 = (i4 & 7) * 4;
        int p = pc >> 6, c = pc & 63;
        float4 xv = *(const float4*)(x_in + (size_t)((b * 4 + p) * 64 + c) * HW + pos0 + t4);
        float xs[4] = {xv.x, xv.y, xv.z, xv.w};
#pragma unroll
        for (int j = 0; j < 4; ++j) {
            int row = (t4 + j) * 4 + p;
            __nv_bfloat16 hh, ll;
            bsplit(xs[j], hh, ll);
            aHi[row * 72 + c] = hh;
            aLo[row * 72 + c] = ll;
        }
    }
    if (tid < 128) {
        int p = tid >> 5, t = tid & 31;
        mb_s[t * 4 + p] = g_mb[(size_t)(b * 4 + p) * HW + pos0 + t];
    }
    if (tid < 64) sb[tid] = b_proj[tid];
    if (tid < 8) sr[tid] = rescale[tid];
    __syncthreads();

    int lane = tid & 31, wid = tid >> 5;
    int gid = lane >> 2, tig = lane & 3;
    const int t = tid >> 3, h = tid & 7;
    int wm = wid & 3, wn = wid >> 2;
    int row0 = wm * 32, col0 = wn * 32;

#define GEMM64(EPILOG)                                                          \
    {                                                                           \
        float acc[2][4][4];                                                     \
        _Pragma("unroll")                                                       \
        for (int mt = 0; mt < 2; ++mt)                                          \
            _Pragma("unroll")                                                   \
            for (int nb = 0; nb < 4; ++nb)                                      \
                _Pragma("unroll")                                               \
                for (int i = 0; i < 4; ++i) acc[mt][nb][i] = 0.f;               \
        _Pragma("unroll")                                                       \
        for (int kk = 0; kk < 4; ++kk) {                                        \
            unsigned aH[2][4], aL[2][4];                                        \
            _Pragma("unroll")                                                   \
            for (int mt = 0; mt < 2; ++mt) {                                    \
                const __nv_bfloat16* ab = aHi + (row0 + mt * 16 + gid) * 72 + kk * 16 + 2 * tig; \
                aH[mt][0] = *(const unsigned*)(ab);                             \
                aH[mt][1] = *(const unsigned*)(ab + 8 * 72);                    \
                aH[mt][2] = *(const unsigned*)(ab + 8);                         \
                aH[mt][3] = *(const unsigned*)(ab + 8 * 72 + 8);                \
                const __nv_bfloat16* al = aLo + (row0 + mt * 16 + gid) * 72 + kk * 16 + 2 * tig; \
                aL[mt][0] = *(const unsigned*)(al);                             \
                aL[mt][1] = *(const unsigned*)(al + 8 * 72);                    \
                aL[mt][2] = *(const unsigned*)(al + 8);                         \
                aL[mt][3] = *(const unsigned*)(al + 8 * 72 + 8);                \
            }                                                                   \
            _Pragma("unroll")                                                   \
            for (int nb = 0; nb < 4; ++nb) {                                    \
                int n = col0 + nb * 8 + gid;                                    \
                const __nv_bfloat16* bh = bHi + n * 72 + kk * 16 + 2 * tig;     \
                unsigned bh0 = *(const unsigned*)(bh);                          \
                unsigned bh1 = *(const unsigned*)(bh + 8);                      \
                const __nv_bfloat16* bl = bLo + n * 72 + kk * 16 + 2 * tig;     \
                unsigned bl0 = *(const unsigned*)(bl);                          \
                unsigned bl1 = *(const unsigned*)(bl + 8);                      \
                _Pragma("unroll")                                               \
                for (int mt = 0; mt < 2; ++mt) {                                \
                    mma16816(acc[mt][nb], aH[mt], bh0, bh1);                    \
                    mma16816(acc[mt][nb], aH[mt], bl0, bl1);                    \
                    mma16816(acc[mt][nb], aL[mt], bh0, bh1);                    \
                }                                                               \
            }                                                                   \
        }                                                                       \
        EPILOG                                                                  \
    }

#define EPI_CF                                                                  \
        _Pragma("unroll")                                                       \
        for (int mt = 0; mt < 2; ++mt)                                          \
            _Pragma("unroll")                                                   \
            for (int nb = 0; nb < 4; ++nb) {                                    \
                int row = row0 + mt * 16 + gid;                                 \
                int col = col0 + nb * 8 + 2 * tig;                              \
                float* dst = Cf + row * 68 + col;                               \
                *(float2*)dst = make_float2(acc[mt][nb][0], acc[mt][nb][1]);    \
                *(float2*)(dst + 8 * 68) = make_float2(acc[mt][nb][2], acc[mt][nb][3]); \
            }

    // ===== phase 1: Q GEMM =====
    GEMM64(EPI_CF)
    __syncthreads();

    // read q -> regs; stage B = wk
    float q[4][8];
#pragma unroll
    for (int p = 0; p < 4; ++p) {
        const float* cr = Cf + (t * 4 + p) * 68 + h * 8;
#pragma unroll
        for (int j2 = 0; j2 < 4; ++j2) {
            float2 qq = *(const float2*)(cr + 2 * j2);
            q[p][2 * j2] = qq.x; q[p][2 * j2 + 1] = qq.y;
        }
    }
    for (int i = tid; i < 4096; i += 256) {
        int n = i >> 6, c = i & 63;
        __nv_bfloat16 hh, ll;
        bsplit(wk[i], hh, ll);
        bHi[n * 72 + c] = hh;
        bLo[n * 72 + c] = ll;
    }
    __syncthreads();

    // ===== phase 2: K GEMM =====
    GEMM64(EPI_CF)
    __syncthreads();

    // read k; normalize; softmax -> att; stage B = wv
    float att[4][4];
    {
        float k[4][8];
#pragma unroll
        for (int p = 0; p < 4; ++p) {
            const float* cr = Cf + (t * 4 + p) * 68 + h * 8;
#pragma unroll
            for (int j2 = 0; j2 < 4; ++j2) {
                float2 kk2 = *(const float2*)(cr + 2 * j2);
                k[p][2 * j2] = kk2.x; k[p][2 * j2 + 1] = kk2.y;
            }
        }
#pragma unroll
        for (int p = 0; p < 4; ++p) {
            float sq = 0.f, sk = 0.f;
#pragma unroll
            for (int j = 0; j < 8; ++j) { sq += q[p][j] * q[p][j]; sk += k[p][j] * k[p][j]; }
            float iq = 1.0f / fmaxf(sqrtf(sq), 1e-12f);
            float ik = 1.0f / fmaxf(sqrtf(sk), 1e-12f);
#pragma unroll
            for (int j = 0; j < 8; ++j) { q[p][j] *= iq; k[p][j] *= ik; }
        }
        float rh = sr[h];
        float mbl[4];
#pragma unroll
        for (int p = 0; p < 4; ++p) mbl[p] = mb_s[t * 4 + p];
#pragma unroll
        for (int p = 0; p < 4; ++p) {
#pragma unroll
            for (int pq = 0; pq < 4; ++pq) {
                float d = 0.f;
#pragma unroll
                for (int j = 0; j < 8; ++j) d += q[p][j] * k[pq][j];
                att[p][pq] = d * rh + (mbl[pq] - mbl[p]);
            }
            float mx = fmaxf(fmaxf(att[p][0], att[p][1]), fmaxf(att[p][2], att[p][3]));
            float s = 0.f;
#pragma unroll
            for (int pq = 0; pq < 4; ++pq) { att[p][pq] = __expf(att[p][pq] - mx); s += att[p][pq]; }
            float inv = 1.0f / s;
#pragma unroll
            for (int pq = 0; pq < 4; ++pq) att[p][pq] *= inv;
        }
    }
    for (int i = tid; i < 4096; i += 256) {
        int n = i >> 6, c = i & 63;
        __nv_bfloat16 hh, ll;
        bsplit(wv[i], hh, ll);
        bHi[n * 72 + c] = hh;
        bLo[n * 72 + c] = ll;
    }
    __syncthreads();

    // ===== phase 3: V GEMM =====
    GEMM64(EPI_CF)
    __syncthreads();

    // o = att*v -> A (exclusive slots); stage B = wp
    {
#pragma unroll
        for (int j = 0; j < 8; ++j) {
            int c = h * 8 + j;
            float vv[4];
#pragma unroll
            for (int p = 0; p < 4; ++p) vv[p] = Cf[(t * 4 + p) * 68 + c];
#pragma unroll
            for (int p = 0; p < 4; ++p) {
                float o = att[p][0] * vv[0] + att[p][1] * vv[1] +
                          att[p][2] * vv[2] + att[p][3] * vv[3];
                __nv_bfloat16 hh, ll;
                bsplit(o, hh, ll);
                int row = t * 4 + p;
                aHi[row * 72 + c] = hh;
                aLo[row * 72 + c] = ll;
            }
        }
    }
    for (int i = tid; i < 4096; i += 256) {
        int n = i >> 6, c = i & 63;
        __nv_bfloat16 hh, ll;
        bsplit(wp[i], hh, ll);
        bHi[n * 72 + c] = hh;
        bLo[n * 72 + c] = ll;
    }
    __syncthreads();

    // ===== phase 4: P GEMM -> out staging =====
#define EPI_OUT                                                                 \
        __syncthreads();                                                        \
        _Pragma("unroll")                                                       \
        for (int mt = 0; mt < 2; ++mt)                                          \
            _Pragma("unroll")                                                   \
            for (int nb = 0; nb < 4; ++nb) {                                    \
                int row = row0 + mt * 16 + gid;                                 \
                int col = col0 + nb * 8 + 2 * tig;                              \
                int tt = row >> 2, p = row & 3;                                 \
                out_s[(p * 64 + col) * 32 + tt]         = acc[mt][nb][0] + sb[col]; \
                out_s[(p * 64 + col + 1) * 32 + tt]     = acc[mt][nb][1] + sb[col + 1]; \
                out_s[(p * 64 + col) * 32 + tt + 2]     = acc[mt][nb][2] + sb[col]; \
                out_s[(p * 64 + col + 1) * 32 + tt + 2] = acc[mt][nb][3] + sb[col + 1]; \
            }

    GEMM64(EPI_OUT)
    __syncthreads();

    // coalesced writeback
    for (int i4 = tid; i4 < 2048; i4 += 256) {
        int pc = i4 >> 3;
        int t4 = (i4 & 7) * 4;
        int p = pc >> 6, c = pc & 63;
        float4 vv = *(const float4*)(out_s + pc * 32 + t4);
        *(float4*)(out + (size_t)((b * 4 + p) * 64 + c) * HW + pos0 + t4) = vv;
    }
}

// ---------------------------------------------------------------------------
extern "C" void kernel_launch(void* const* d_in, const int* in_sizes, int n_in,
                              void* d_out, int out_size) {
    (void)in_sizes; (void)n_in; (void)out_size;
    const float* x_in   = (const float*)d_in[0];
    const float* mask   = (const float*)d_in[1];
    const float* wq     = (const float*)d_in[2];
    const float* wk     = (const float*)d_in[3];
    const float* wv     = (const float*)d_in[4];
    const float* w_proj = (const float*)d_in[5];
    const float* b_proj = (const float*)d_in[6];
    const float* rescale= (const float*)d_in[7];
    const float* dw_w   = (const float*)d_in[8];
    const float* dw_b   = (const float*)d_in[9];
    const float* pw_w   = (const float*)d_in[10];
    const float* pw_b   = (const float*)d_in[11];
    float* out = (float*)d_out;

    cudaFuncSetAttribute(attn_fused, cudaFuncAttributeMaxDynamicSharedMemorySize,
                         ATTN_SMEM_BYTES);

    mask_kernel3<<<dim3(8, 16), 256>>>(mask, dw_w, dw_b, pw_w, pw_b);
    attn_fused<<<dim3(512, Bn), 256, ATTN_SMEM_BYTES>>>(
        x_in, wq, wk, wv, w_proj, b_proj, rescale, out);
}

// round 12
// speedup vs baseline: 2.0498x; 1.2521x over previous
#include <cuda_runtime.h>
#include <cuda_bf16.h>
#include <math.h>

#define Bn 4
#define Pp 4
#define Cc 64
#define NH 8
#define Hh 128
#define Wd 128
#define HW 16384

// scratch (no cudaMalloc allowed)
__device__ float g_mb[16 * HW];                 // mask bias per (b,p,pos)
__device__ __nv_bfloat16 g_wHi[4][4096];        // pre-split weights hi
__device__ __nv_bfloat16 g_wLo[4][4096];        // pre-split weights lo

// ---------------------------------------------------------------------------
// helpers
// ---------------------------------------------------------------------------
__device__ __forceinline__ void bsplit(float f, __nv_bfloat16& h, __nv_bfloat16& l) {
    h = __float2bfloat16(f);
    l = __float2bfloat16(f - __bfloat162float(h));
}

__device__ __forceinline__ void mma16816(float* c, const unsigned* a,
                                         unsigned b0, unsigned b1) {
    asm volatile(
        "mma.sync.aligned.m16n8k16.row.col.f32.bf16.bf16.f32 "
        "{%0,%1,%2,%3}, {%4,%5,%6,%7}, {%8,%9}, {%0,%1,%2,%3};"
        : "+f"(c[0]), "+f"(c[1]), "+f"(c[2]), "+f"(c[3])
        : "r"(a[0]), "r"(a[1]), "r"(a[2]), "r"(a[3]), "r"(b0), "r"(b1));
}

// ---------------------------------------------------------------------------
// Kernel 0: pre-split all four weight matrices into bf16 hi/lo.
// ---------------------------------------------------------------------------
__global__ void wsplit_kernel(const float* __restrict__ wq,
                              const float* __restrict__ wk,
                              const float* __restrict__ wv,
                              const float* __restrict__ wp) {
    int i = blockIdx.x * 256 + threadIdx.x;
    const float* Ws[4] = {wq, wk, wv, wp};
#pragma unroll
    for (int m = 0; m < 4; ++m) {
        __nv_bfloat16 h, l;
        bsplit(Ws[m][i], h, l);
        g_wHi[m][i] = h;
        g_wLo[m][i] = l;
    }
}

// ---------------------------------------------------------------------------
// Kernel 1: mask branch, row-band layout (R11, known-good ~55us).
// ---------------------------------------------------------------------------
#define TS (18 * 132)
__global__ void __launch_bounds__(256)
mask_kernel3(const float* __restrict__ mask,
             const float* __restrict__ dw_w,
             const float* __restrict__ dw_b,
             const float* __restrict__ pw_w,
             const float* __restrict__ pw_b) {
    __shared__ float tilef[4 * TS];
    __shared__ float sdw[Cc][9];
    __shared__ float sdb[Cc];
    __shared__ float swbar[Cc + 1];
    __shared__ float wpart[4][Cc];

    int tid = threadIdx.x;
    int h0 = blockIdx.x * 16;
    int bp = blockIdx.y;

    for (int i = tid; i < Cc * 9; i += 256) sdw[i / 9][i % 9] = dw_w[i];
    for (int i = tid; i < Cc; i += 256) sdb[i] = dw_b[i];
    {
        int c = tid & 63, dg = tid >> 6;
        float s = 0.f;
        for (int d = dg * 16; d < dg * 16 + 16; ++d) s += pw_w[d * Cc + c];
        wpart[dg][c] = s;
    }
    if (tid >= 192 && tid < 224) {
        float s = pw_b[tid - 192] + pw_b[tid - 192 + 32];
#pragma unroll
        for (int o = 16; o > 0; o >>= 1)
            s += __shfl_down_sync(0xFFFFFFFFu, s, o);
        if (tid == 192) swbar[Cc] = s * (1.0f / Cc);
    }
    if (tid < 72) {
        int cc = tid / 18, r = tid % 18;
        tilef[cc * TS + r * 132 + 0] = 0.f;
        tilef[cc * TS + r * 132 + 129] = 0.f;
    }
    __syncthreads();
    if (tid < Cc)
        swbar[tid] = (wpart[0][tid] + wpart[1][tid] + wpart[2][tid] + wpart[3][tid]) * (1.0f / Cc);

    const int col = tid & 127;
    const int rowgrp = tid >> 7;
    const float* base = mask + (size_t)bp * Cc * HW;

    float acc[8];
#pragma unroll
    for (int j = 0; j < 8; ++j) acc[j] = 0.f;

    for (int cb = 0; cb < Cc; cb += 4) {
        __syncthreads();
#pragma unroll
        for (int it = 0; it < 9; ++it) {
            int r = it * 2 + rowgrp;
            int gh = h0 + r - 1;
            bool ok = (gh >= 0 && gh < Hh);
            const float* src = base + (size_t)cb * HW + gh * Wd + col;
            float* dst = tilef + r * 132 + col + 1;
#pragma unroll
            for (int cc = 0; cc < 4; ++cc)
                dst[cc * TS] = ok ? src[(size_t)cc * HW] : 0.f;
        }
        __syncthreads();
#pragma unroll
        for (int cc = 0; cc < 4; ++cc) {
            int c = cb + cc;
            const float* tb = tilef + cc * TS + col;
            float w0 = sdw[c][0], w1 = sdw[c][1], w2 = sdw[c][2];
            float w3 = sdw[c][3], w4 = sdw[c][4], w5 = sdw[c][5];
            float w6 = sdw[c][6], w7 = sdw[c][7], w8 = sdw[c][8];
            float bias = sdb[c], wb = swbar[c];
#pragma unroll
            for (int j = 0; j < 8; ++j) {
                int lr = rowgrp * 8 + j;
                const float* t0 = tb + lr * 132;
                float y = bias
                    + t0[0] * w0 + t0[1] * w1 + t0[2] * w2
                    + t0[132] * w3 + t0[133] * w4 + t0[134] * w5
                    + t0[264] * w6 + t0[265] * w7 + t0[266] * w8;
                float g = 0.5f * y * (1.0f + erff(y * 0.70710678118654752f));
                acc[j] += wb * g;
            }
        }
    }
    float bb = swbar[Cc];
#pragma unroll
    for (int j = 0; j < 8; ++j) {
        int lr = rowgrp * 8 + j;
        g_mb[(size_t)bp * HW + (h0 + lr) * Wd + col] = acc[j] + bb;
    }
}

// ---------------------------------------------------------------------------
// Kernel 2: fused per-32-token tile, double-buffered B, pre-split weights,
// restages hidden behind midsections. 8 barriers.
// smem (bf16 elem offsets):
//   aHi @0 (128x72), aLo @9216
//   b0Hi @18432 (64x72), b0Lo @23040      wq -> wv
//   b1Hi @27648 (64x72), b1Lo @32256      wk -> wp
//   Cf fp32 @byte 73728, 128x68 = 34816B
//   mb_s[128] sb[64] sr[8] after Cf
// total = 109344 B -> 2 CTAs/SM
// ---------------------------------------------------------------------------
#define ATTN_SMEM_BYTES 109344

__device__ __forceinline__ void stage_wpre(__nv_bfloat16* dHi, __nv_bfloat16* dLo,
                                           int m, int tid) {
    const uint4* sHi = (const uint4*)g_wHi[m];
    const uint4* sLo = (const uint4*)g_wLo[m];
#pragma unroll
    for (int s = 0; s < 2; ++s) {
        int i8 = tid + s * 256;          // 512 groups of 8 bf16
        int n = i8 >> 3, c8 = (i8 & 7) * 8;
        uint4 vH = sHi[i8];
        uint4 vL = sLo[i8];
        *(uint4*)(dHi + n * 72 + c8) = vH;
        *(uint4*)(dLo + n * 72 + c8) = vL;
    }
}

__global__ void __launch_bounds__(256, 2)
attn_fused(const float* __restrict__ x_in,
           const float* __restrict__ b_proj,
           const float* __restrict__ rescale,
           float* __restrict__ out) {
    extern __shared__ __nv_bfloat16 smb[];
    __nv_bfloat16* aHi  = smb;
    __nv_bfloat16* aLo  = smb + 9216;
    __nv_bfloat16* b0Hi = smb + 18432;
    __nv_bfloat16* b0Lo = smb + 23040;
    __nv_bfloat16* b1Hi = smb + 27648;
    __nv_bfloat16* b1Lo = smb + 32256;
    float* Cf    = (float*)(smb + 36864);
    float* mb_s  = Cf + 8704;
    float* sb    = mb_s + 128;
    float* sr    = sb + 64;
    float* out_s = Cf;

    int tid = threadIdx.x;
    int b = blockIdx.y;
    int pos0 = blockIdx.x * 32;

    // stage b0=wq, b1=wk (pre-split copies)
    stage_wpre(b0Hi, b0Lo, 0, tid);
    stage_wpre(b1Hi, b1Lo, 1, tid);
    // stage A: batch 8 LDG.128 first, then convert
    {
        float4 xr[8];
#pragma unroll
        for (int s = 0; s < 8; ++s) {
            int i4 = tid + s * 256;
            int pc = i4 >> 3;
            int t4 = (i4 & 7) * 4;
            int p = pc >> 6, c = pc & 63;
            xr[s] = *(const float4*)(x_in + (size_t)((b * 4 + p) * 64 + c) * HW + pos0 + t4);
        }
#pragma unroll
        for (int s = 0; s < 8; ++s) {
            int i4 = tid + s * 256;
            int pc = i4 >> 3;
            int t4 = (i4 & 7) * 4;
            int p = pc >> 6, c = pc & 63;
            float xs[4] = {xr[s].x, xr[s].y, xr[s].z, xr[s].w};
#pragma unroll
            for (int j = 0; j < 4; ++j) {
                int row = (t4 + j) * 4 + p;
                __nv_bfloat16 hh, ll;
                bsplit(xs[j], hh, ll);
                aHi[row * 72 + c] = hh;
                aLo[row * 72 + c] = ll;
            }
        }
    }
    if (tid < 128) {
        int p = tid >> 5, t = tid & 31;
        mb_s[t * 4 + p] = g_mb[(size_t)(b * 4 + p) * HW + pos0 + t];
    }
    if (tid < 64) sb[tid] = b_proj[tid];
    if (tid < 8) sr[tid] = rescale[tid];
    __syncthreads();                                        // (1)

    int lane = tid & 31, wid = tid >> 5;
    int gid = lane >> 2, tig = lane & 3;
    const int t = tid >> 3, h = tid & 7;
    int wm = wid & 3, wn = wid >> 2;
    int row0 = wm * 32, col0 = wn * 32;

#define GEMM64(BH, BL, EPILOG)                                                  \
    {                                                                           \
        float acc[2][4][4];                                                     \
        _Pragma("unroll")                                                       \
        for (int mt = 0; mt < 2; ++mt)                                          \
            _Pragma("unroll")                                                   \
            for (int nb = 0; nb < 4; ++nb)                                      \
                _Pragma("unroll")                                               \
                for (int i = 0; i < 4; ++i) acc[mt][nb][i] = 0.f;               \
        _Pragma("unroll")                                                       \
        for (int kk = 0; kk < 4; ++kk) {                                        \
            unsigned aH[2][4], aL[2][4];                                        \
            _Pragma("unroll")                                                   \
            for (int mt = 0; mt < 2; ++mt) {                                    \
                const __nv_bfloat16* ab = aHi + (row0 + mt * 16 + gid) * 72 + kk * 16 + 2 * tig; \
                aH[mt][0] = *(const unsigned*)(ab);                             \
                aH[mt][1] = *(const unsigned*)(ab + 8 * 72);                    \
                aH[mt][2] = *(const unsigned*)(ab + 8);                         \
                aH[mt][3] = *(const unsigned*)(ab + 8 * 72 + 8);                \
                const __nv_bfloat16* al = aLo + (row0 + mt * 16 + gid) * 72 + kk * 16 + 2 * tig; \
                aL[mt][0] = *(const unsigned*)(al);                             \
                aL[mt][1] = *(const unsigned*)(al + 8 * 72);                    \
                aL[mt][2] = *(const unsigned*)(al + 8);                         \
                aL[mt][3] = *(const unsigned*)(al + 8 * 72 + 8);                \
            }                                                                   \
            _Pragma("unroll")                                                   \
            for (int nb = 0; nb < 4; ++nb) {                                    \
                int n = col0 + nb * 8 + gid;                                    \
                const __nv_bfloat16* bh = (BH) + n * 72 + kk * 16 + 2 * tig;    \
                unsigned bh0 = *(const unsigned*)(bh);                          \
                unsigned bh1 = *(const unsigned*)(bh + 8);                      \
                const __nv_bfloat16* bl = (BL) + n * 72 + kk * 16 + 2 * tig;    \
                unsigned bl0 = *(const unsigned*)(bl);                          \
                unsigned bl1 = *(const unsigned*)(bl + 8);                      \
                _Pragma("unroll")                                               \
                for (int mt = 0; mt < 2; ++mt) {                                \
                    mma16816(acc[mt][nb], aH[mt], bh0, bh1);                    \
                    mma16816(acc[mt][nb], aH[mt], bl0, bl1);                    \
                    mma16816(acc[mt][nb], aL[mt], bh0, bh1);                    \
                }                                                               \
            }                                                                   \
        }                                                                       \
        EPILOG                                                                  \
    }

#define EPI_CF                                                                  \
        _Pragma("unroll")                                                       \
        for (int mt = 0; mt < 2; ++mt)                                          \
            _Pragma("unroll")                                                   \
            for (int nb = 0; nb < 4; ++nb) {                                    \
                int row = row0 + mt * 16 + gid;                                 \
                int col = col0 + nb * 8 + 2 * tig;                              \
                float* dst = Cf + row * 68 + col;                               \
                *(float2*)dst = make_float2(acc[mt][nb][0], acc[mt][nb][1]);    \
                *(float2*)(dst + 8 * 68) = make_float2(acc[mt][nb][2], acc[mt][nb][3]); \
            }

    // ===== Q GEMM (B=b0) =====
    GEMM64(b0Hi, b0Lo, EPI_CF)
    __syncthreads();                                        // (2)

    // mid A: read q -> regs; restage b0 <- wv (hidden)
    float q[4][8];
#pragma unroll
    for (int p = 0; p < 4; ++p) {
        const float* cr = Cf + (t * 4 + p) * 68 + h * 8;
#pragma unroll
        for (int j2 = 0; j2 < 4; ++j2) {
            float2 qq = *(const float2*)(cr + 2 * j2);
            q[p][2 * j2] = qq.x; q[p][2 * j2 + 1] = qq.y;
        }
    }
    stage_wpre(b0Hi, b0Lo, 2, tid);
    __syncthreads();                                        // (3)

    // ===== K GEMM (B=b1) =====
    GEMM64(b1Hi, b1Lo, EPI_CF)
    __syncthreads();                                        // (4)

    // mid B: read k, normalize, softmax -> att; restage b1 <- wp (hidden)
    float att[4][4];
    {
        float k[4][8];
#pragma unroll
        for (int p = 0; p < 4; ++p) {
            const float* cr = Cf + (t * 4 + p) * 68 + h * 8;
#pragma unroll
            for (int j2 = 0; j2 < 4; ++j2) {
                float2 kk2 = *(const float2*)(cr + 2 * j2);
                k[p][2 * j2] = kk2.x; k[p][2 * j2 + 1] = kk2.y;
            }
        }
#pragma unroll
        for (int p = 0; p < 4; ++p) {
            float sq = 0.f, sk = 0.f;
#pragma unroll
            for (int j = 0; j < 8; ++j) { sq += q[p][j] * q[p][j]; sk += k[p][j] * k[p][j]; }
            float iq = 1.0f / fmaxf(sqrtf(sq), 1e-12f);
            float ik = 1.0f / fmaxf(sqrtf(sk), 1e-12f);
#pragma unroll
            for (int j = 0; j < 8; ++j) { q[p][j] *= iq; k[p][j] *= ik; }
        }
        float rh = sr[h];
        float mbl[4];
#pragma unroll
        for (int p = 0; p < 4; ++p) mbl[p] = mb_s[t * 4 + p];
#pragma unroll
        for (int p = 0; p < 4; ++p) {
#pragma unroll
            for (int pq = 0; pq < 4; ++pq) {
                float d = 0.f;
#pragma unroll
                for (int j = 0; j < 8; ++j) d += q[p][j] * k[pq][j];
                att[p][pq] = d * rh + (mbl[pq] - mbl[p]);
            }
            float mx = fmaxf(fmaxf(att[p][0], att[p][1]), fmaxf(att[p][2], att[p][3]));
            float s = 0.f;
#pragma unroll
            for (int pq = 0; pq < 4; ++pq) { att[p][pq] = __expf(att[p][pq] - mx); s += att[p][pq]; }
            float inv = 1.0f / s;
#pragma unroll
            for (int pq = 0; pq < 4; ++pq) att[p][pq] *= inv;
        }
    }
    stage_wpre(b1Hi, b1Lo, 3, tid);
    __syncthreads();                                        // (5)

    // ===== V GEMM (B=b0) =====
    GEMM64(b0Hi, b0Lo, EPI_CF)
    __syncthreads();                                        // (6)

    // mid C: o = att*v -> A (exclusive slots)
    {
#pragma unroll
        for (int j = 0; j < 8; ++j) {
            int c = h * 8 + j;
            float vv[4];
#pragma unroll
            for (int p = 0; p < 4; ++p) vv[p] = Cf[(t * 4 + p) * 68 + c];
#pragma unroll
            for (int p = 0; p < 4; ++p) {
                float o = att[p][0] * vv[0] + att[p][1] * vv[1] +
                          att[p][2] * vv[2] + att[p][3] * vv[3];
                __nv_bfloat16 hh, ll;
                bsplit(o, hh, ll);
                int row = t * 4 + p;
                aHi[row * 72 + c] = hh;
                aLo[row * 72 + c] = ll;
            }
        }
    }
    __syncthreads();                                        // (7)

    // ===== P GEMM (B=b1) -> out staging =====
#define EPI_OUT                                                                 \
        _Pragma("unroll")                                                       \
        for (int mt = 0; mt < 2; ++mt)                                          \
            _Pragma("unroll")                                                   \
            for (int nb = 0; nb < 4; ++nb) {                                    \
                int row = row0 + mt * 16 + gid;                                 \
                int col = col0 + nb * 8 + 2 * tig;                              \
                int tt = row >> 2, p = row & 3;                                 \
                out_s[(p * 64 + col) * 32 + tt]         = acc[mt][nb][0] + sb[col]; \
                out_s[(p * 64 + col + 1) * 32 + tt]     = acc[mt][nb][1] + sb[col + 1]; \
                out_s[(p * 64 + col) * 32 + tt + 2]     = acc[mt][nb][2] + sb[col]; \
                out_s[(p * 64 + col + 1) * 32 + tt + 2] = acc[mt][nb][3] + sb[col + 1]; \
            }

    GEMM64(b1Hi, b1Lo, EPI_OUT)
    __syncthreads();                                        // (8)

    // coalesced writeback
    for (int i4 = tid; i4 < 2048; i4 += 256) {
        int pc = i4 >> 3;
        int t4 = (i4 & 7) * 4;
        int p = pc >> 6, c = pc & 63;
        float4 vv = *(const float4*)(out_s + pc * 32 + t4);
        *(float4*)(out + (size_t)((b * 4 + p) * 64 + c) * HW + pos0 + t4) = vv;
    }
}

// ---------------------------------------------------------------------------
extern "C" void kernel_launch(void* const* d_in, const int* in_sizes, int n_in,
                              void* d_out, int out_size) {
    (void)in_sizes; (void)n_in; (void)out_size;
    const float* x_in   = (const float*)d_in[0];
    const float* mask   = (const float*)d_in[1];
    const float* wq     = (const float*)d_in[2];
    const float* wk     = (const float*)d_in[3];
    const float* wv     = (const float*)d_in[4];
    const float* w_proj = (const float*)d_in[5];
    const float* b_proj = (const float*)d_in[6];
    const float* rescale= (const float*)d_in[7];
    const float* dw_w   = (const float*)d_in[8];
    const float* dw_b   = (const float*)d_in[9];
    const float* pw_w   = (const float*)d_in[10];
    const float* pw_b   = (const float*)d_in[11];
    float* out = (float*)d_out;

    cudaFuncSetAttribute(attn_fused, cudaFuncAttributeMaxDynamicSharedMemorySize,
                         ATTN_SMEM_BYTES);

    wsplit_kernel<<<16, 256>>>(wq, wk, wv, w_proj);
    mask_kernel3<<<dim3(8, 16), 256>>>(mask, dw_w, dw_b, pw_w, pw_b);
    attn_fused<<<dim3(512, Bn), 256, ATTN_SMEM_BYTES>>>(
        x_in, b_proj, rescale, out);
}

// round 13
// speedup vs baseline: 2.1788x; 1.0629x over previous
#include <cuda_runtime.h>
#include <cuda_bf16.h>
#include <math.h>

#define Bn 4
#define Pp 4
#define Cc 64
#define NH 8
#define Hh 128
#define Wd 128
#define HW 16384

// scratch (no cudaMalloc allowed)
__device__ float g_mb[16 * HW];                 // mask bias per (b,p,pos)
__device__ __nv_bfloat16 g_wHi[4][4096];        // pre-split weights hi
__device__ __nv_bfloat16 g_wLo[4][4096];        // pre-split weights lo

// ---------------------------------------------------------------------------
// helpers
// ---------------------------------------------------------------------------
__device__ __forceinline__ void bsplit(float f, __nv_bfloat16& h, __nv_bfloat16& l) {
    h = __float2bfloat16(f);
    l = __float2bfloat16(f - __bfloat162float(h));
}

__device__ __forceinline__ void mma16816(float* c, const unsigned* a,
                                         unsigned b0, unsigned b1) {
    asm volatile(
        "mma.sync.aligned.m16n8k16.row.col.f32.bf16.bf16.f32 "
        "{%0,%1,%2,%3}, {%4,%5,%6,%7}, {%8,%9}, {%0,%1,%2,%3};"
        : "+f"(c[0]), "+f"(c[1]), "+f"(c[2]), "+f"(c[3])
        : "r"(a[0]), "r"(a[1]), "r"(a[2]), "r"(a[3]), "r"(b0), "r"(b1));
}

// ---------------------------------------------------------------------------
// Kernel 1: mask branch (R11 row-band layout) + folded weight pre-split.
// ---------------------------------------------------------------------------
#define TS (18 * 132)
__global__ void __launch_bounds__(256)
mask_kernel3(const float* __restrict__ mask,
             const float* __restrict__ dw_w,
             const float* __restrict__ dw_b,
             const float* __restrict__ pw_w,
             const float* __restrict__ pw_b,
             const float* __restrict__ wq,
             const float* __restrict__ wk,
             const float* __restrict__ wv,
             const float* __restrict__ wp) {
    __shared__ float tilef[4 * TS];
    __shared__ float sdw[Cc][9];
    __shared__ float sdb[Cc];
    __shared__ float swbar[Cc + 1];
    __shared__ float wpart[4][Cc];

    int tid = threadIdx.x;
    int h0 = blockIdx.x * 16;
    int bp = blockIdx.y;

    // fold wsplit: blocks with blockIdx.x==0 split 256 weight elems each
    if (blockIdx.x == 0) {
        int i = bp * 256 + tid;
        const float* Ws[4] = {wq, wk, wv, wp};
#pragma unroll
        for (int m = 0; m < 4; ++m) {
            __nv_bfloat16 h, l;
            bsplit(Ws[m][i], h, l);
            g_wHi[m][i] = h;
            g_wLo[m][i] = l;
        }
    }

    for (int i = tid; i < Cc * 9; i += 256) sdw[i / 9][i % 9] = dw_w[i];
    for (int i = tid; i < Cc; i += 256) sdb[i] = dw_b[i];
    {
        int c = tid & 63, dg = tid >> 6;
        float s = 0.f;
        for (int d = dg * 16; d < dg * 16 + 16; ++d) s += pw_w[d * Cc + c];
        wpart[dg][c] = s;
    }
    if (tid >= 192 && tid < 224) {
        float s = pw_b[tid - 192] + pw_b[tid - 192 + 32];
#pragma unroll
        for (int o = 16; o > 0; o >>= 1)
            s += __shfl_down_sync(0xFFFFFFFFu, s, o);
        if (tid == 192) swbar[Cc] = s * (1.0f / Cc);
    }
    if (tid < 72) {
        int cc = tid / 18, r = tid % 18;
        tilef[cc * TS + r * 132 + 0] = 0.f;
        tilef[cc * TS + r * 132 + 129] = 0.f;
    }
    __syncthreads();
    if (tid < Cc)
        swbar[tid] = (wpart[0][tid] + wpart[1][tid] + wpart[2][tid] + wpart[3][tid]) * (1.0f / Cc);

    const int col = tid & 127;
    const int rowgrp = tid >> 7;
    const float* base = mask + (size_t)bp * Cc * HW;

    float acc[8];
#pragma unroll
    for (int j = 0; j < 8; ++j) acc[j] = 0.f;

    for (int cb = 0; cb < Cc; cb += 4) {
        __syncthreads();
#pragma unroll
        for (int it = 0; it < 9; ++it) {
            int r = it * 2 + rowgrp;
            int gh = h0 + r - 1;
            bool ok = (gh >= 0 && gh < Hh);
            const float* src = base + (size_t)cb * HW + gh * Wd + col;
            float* dst = tilef + r * 132 + col + 1;
#pragma unroll
            for (int cc = 0; cc < 4; ++cc)
                dst[cc * TS] = ok ? src[(size_t)cc * HW] : 0.f;
        }
        __syncthreads();
#pragma unroll
        for (int cc = 0; cc < 4; ++cc) {
            int c = cb + cc;
            const float* tb = tilef + cc * TS + col;
            float w0 = sdw[c][0], w1 = sdw[c][1], w2 = sdw[c][2];
            float w3 = sdw[c][3], w4 = sdw[c][4], w5 = sdw[c][5];
            float w6 = sdw[c][6], w7 = sdw[c][7], w8 = sdw[c][8];
            float bias = sdb[c], wb = swbar[c];
#pragma unroll
            for (int j = 0; j < 8; ++j) {
                int lr = rowgrp * 8 + j;
                const float* t0 = tb + lr * 132;
                float y = bias
                    + t0[0] * w0 + t0[1] * w1 + t0[2] * w2
                    + t0[132] * w3 + t0[133] * w4 + t0[134] * w5
                    + t0[264] * w6 + t0[265] * w7 + t0[266] * w8;
                float g = 0.5f * y * (1.0f + erff(y * 0.70710678118654752f));
                acc[j] += wb * g;
            }
        }
    }
    float bb = swbar[Cc];
#pragma unroll
    for (int j = 0; j < 8; ++j) {
        int lr = rowgrp * 8 + j;
        g_mb[(size_t)bp * HW + (h0 + lr) * Wd + col] = acc[j] + bb;
    }
}

// ---------------------------------------------------------------------------
// Kernel 2: fused 16-token tile, 128 threads, 4 CTAs/SM (4-way phase overlap).
// smem (bf16 elem offsets):
//   aHi @0 (64x72), aLo @4608
//   bHi @9216 (64x72), bLo @13824        wq -> wk -> wv -> wp
//   Cf fp32 @byte 36864, 64x68 = 17408B  per-phase C / out staging
//   mb_s[64] sb[64] sr[8] after Cf
// total = 54816 B -> 4 CTAs/SM (219KB)
// ---------------------------------------------------------------------------
#define ATTN_SMEM_BYTES 54816

__device__ __forceinline__ void stage_wpre(__nv_bfloat16* dHi, __nv_bfloat16* dLo,
                                           int m, int tid) {
    const uint4* sHi = (const uint4*)g_wHi[m];
    const uint4* sLo = (const uint4*)g_wLo[m];
#pragma unroll
    for (int s = 0; s < 4; ++s) {
        int i8 = tid + s * 128;          // 512 groups of 8 bf16
        int n = i8 >> 3, c8 = (i8 & 7) * 8;
        uint4 vH = sHi[i8];
        uint4 vL = sLo[i8];
        *(uint4*)(dHi + n * 72 + c8) = vH;
        *(uint4*)(dLo + n * 72 + c8) = vL;
    }
}

__global__ void __launch_bounds__(128, 4)
attn_fused(const float* __restrict__ x_in,
           const float* __restrict__ b_proj,
           const float* __restrict__ rescale,
           float* __restrict__ out) {
    extern __shared__ __nv_bfloat16 smb[];
    __nv_bfloat16* aHi = smb;
    __nv_bfloat16* aLo = smb + 4608;
    __nv_bfloat16* bHi = smb + 9216;
    __nv_bfloat16* bLo = smb + 13824;
    float* Cf    = (float*)(smb + 18432);
    float* mb_s  = Cf + 4352;
    float* sb    = mb_s + 64;
    float* sr    = sb + 64;
    float* out_s = Cf;

    int tid = threadIdx.x;
    int b = blockIdx.y;
    int pos0 = blockIdx.x * 16;

    // stage B = wq
    stage_wpre(bHi, bLo, 0, tid);
    // stage A: batch 8 LDG.128, then convert; rows = t*4+p
    {
        float4 xr[8];
#pragma unroll
        for (int s = 0; s < 8; ++s) {
            int i4 = tid + s * 128;
            int pc = i4 >> 2;
            int t4 = (i4 & 3) * 4;
            int p = pc >> 6, c = pc & 63;
            xr[s] = *(const float4*)(x_in + (size_t)((b * 4 + p) * 64 + c) * HW + pos0 + t4);
        }
#pragma unroll
        for (int s = 0; s < 8; ++s) {
            int i4 = tid + s * 128;
            int pc = i4 >> 2;
            int t4 = (i4 & 3) * 4;
            int p = pc >> 6, c = pc & 63;
            float xs[4] = {xr[s].x, xr[s].y, xr[s].z, xr[s].w};
#pragma unroll
            for (int j = 0; j < 4; ++j) {
                int row = (t4 + j) * 4 + p;
                __nv_bfloat16 hh, ll;
                bsplit(xs[j], hh, ll);
                aHi[row * 72 + c] = hh;
                aLo[row * 72 + c] = ll;
            }
        }
    }
    if (tid < 64) {
        int p = tid >> 4, t = tid & 15;
        mb_s[t * 4 + p] = g_mb[(size_t)(b * 4 + p) * HW + pos0 + t];
        sb[tid] = b_proj[tid];
    }
    if (tid < 8) sr[tid] = rescale[tid];
    __syncthreads();                                        // (1)

    int lane = tid & 31, wid = tid >> 5;
    int gid = lane >> 2, tig = lane & 3;
    const int t = tid >> 3, h = tid & 7;
    int wm = wid & 1, wn = wid >> 1;
    int row0 = wm * 32, col0 = wn * 32;

#define GEMM64(EPILOG)                                                          \
    {                                                                           \
        float acc[2][4][4];                                                     \
        _Pragma("unroll")                                                       \
        for (int mt = 0; mt < 2; ++mt)                                          \
            _Pragma("unroll")                                                   \
            for (int nb = 0; nb < 4; ++nb)                                      \
                _Pragma("unroll")                                               \
                for (int i = 0; i < 4; ++i) acc[mt][nb][i] = 0.f;               \
        _Pragma("unroll")                                                       \
        for (int kk = 0; kk < 4; ++kk) {                                        \
            unsigned aH[2][4], aL[2][4];                                        \
            _Pragma("unroll")                                                   \
            for (int mt = 0; mt < 2; ++mt) {                                    \
                const __nv_bfloat16* ab = aHi + (row0 + mt * 16 + gid) * 72 + kk * 16 + 2 * tig; \
                aH[mt][0] = *(const unsigned*)(ab);                             \
                aH[mt][1] = *(const unsigned*)(ab + 8 * 72);                    \
                aH[mt][2] = *(const unsigned*)(ab + 8);                         \
                aH[mt][3] = *(const unsigned*)(ab + 8 * 72 + 8);                \
                const __nv_bfloat16* al = aLo + (row0 + mt * 16 + gid) * 72 + kk * 16 + 2 * tig; \
                aL[mt][0] = *(const unsigned*)(al);                             \
                aL[mt][1] = *(const unsigned*)(al + 8 * 72);                    \
                aL[mt][2] = *(const unsigned*)(al + 8);                         \
                aL[mt][3] = *(const unsigned*)(al + 8 * 72 + 8);                \
            }                                                                   \
            _Pragma("unroll")                                                   \
            for (int nb = 0; nb < 4; ++nb) {                                    \
                int n = col0 + nb * 8 + gid;                                    \
                const __nv_bfloat16* bh = bHi + n * 72 + kk * 16 + 2 * tig;     \
                unsigned bh0 = *(const unsigned*)(bh);                          \
                unsigned bh1 = *(const unsigned*)(bh + 8);                      \
                const __nv_bfloat16* bl = bLo + n * 72 + kk * 16 + 2 * tig;     \
                unsigned bl0 = *(const unsigned*)(bl);                          \
                unsigned bl1 = *(const unsigned*)(bl + 8);                      \
                _Pragma("unroll")                                               \
                for (int mt = 0; mt < 2; ++mt) {                                \
                    mma16816(acc[mt][nb], aH[mt], bh0, bh1);                    \
                    mma16816(acc[mt][nb], aH[mt], bl0, bl1);                    \
                    mma16816(acc[mt][nb], aL[mt], bh0, bh1);                    \
                }                                                               \
            }                                                                   \
        }                                                                       \
        EPILOG                                                                  \
    }

#define EPI_CF                                                                  \
        _Pragma("unroll")                                                       \
        for (int mt = 0; mt < 2; ++mt)                                          \
            _Pragma("unroll")                                                   \
            for (int nb = 0; nb < 4; ++nb) {                                    \
                int row = row0 + mt * 16 + gid;                                 \
                int col = col0 + nb * 8 + 2 * tig;                              \
                float* dst = Cf + row * 68 + col;                               \
                *(float2*)dst = make_float2(acc[mt][nb][0], acc[mt][nb][1]);    \
                *(float2*)(dst + 8 * 68) = make_float2(acc[mt][nb][2], acc[mt][nb][3]); \
            }

    // ===== Q GEMM =====
    GEMM64(EPI_CF)
    __syncthreads();                                        // (2)

    // mid A: read q -> regs; restage B <- wk
    float q[4][8];
#pragma unroll
    for (int p = 0; p < 4; ++p) {
        const float* cr = Cf + (t * 4 + p) * 68 + h * 8;
#pragma unroll
        for (int j2 = 0; j2 < 4; ++j2) {
            float2 qq = *(const float2*)(cr + 2 * j2);
            q[p][2 * j2] = qq.x; q[p][2 * j2 + 1] = qq.y;
        }
    }
    stage_wpre(bHi, bLo, 1, tid);
    __syncthreads();                                        // (3)

    // ===== K GEMM =====
    GEMM64(EPI_CF)
    __syncthreads();                                        // (4)

    // mid B: read k, normalize, softmax -> att; restage B <- wv
    float att[4][4];
    {
        float k[4][8];
#pragma unroll
        for (int p = 0; p < 4; ++p) {
            const float* cr = Cf + (t * 4 + p) * 68 + h * 8;
#pragma unroll
            for (int j2 = 0; j2 < 4; ++j2) {
                float2 kk2 = *(const float2*)(cr + 2 * j2);
                k[p][2 * j2] = kk2.x; k[p][2 * j2 + 1] = kk2.y;
            }
        }
#pragma unroll
        for (int p = 0; p < 4; ++p) {
            float sq = 0.f, sk = 0.f;
#pragma unroll
            for (int j = 0; j < 8; ++j) { sq += q[p][j] * q[p][j]; sk += k[p][j] * k[p][j]; }
            float iq = 1.0f / fmaxf(sqrtf(sq), 1e-12f);
            float ik = 1.0f / fmaxf(sqrtf(sk), 1e-12f);
#pragma unroll
            for (int j = 0; j < 8; ++j) { q[p][j] *= iq; k[p][j] *= ik; }
        }
        float rh = sr[h];
        float mbl[4];
#pragma unroll
        for (int p = 0; p < 4; ++p) mbl[p] = mb_s[t * 4 + p];
#pragma unroll
        for (int p = 0; p < 4; ++p) {
#pragma unroll
            for (int pq = 0; pq < 4; ++pq) {
                float d = 0.f;
#pragma unroll
                for (int j = 0; j < 8; ++j) d += q[p][j] * k[pq][j];
                att[p][pq] = d * rh + (mbl[pq] - mbl[p]);
            }
            float mx = fmaxf(fmaxf(att[p][0], att[p][1]), fmaxf(att[p][2], att[p][3]));
            float s = 0.f;
#pragma unroll
            for (int pq = 0; pq < 4; ++pq) { att[p][pq] = __expf(att[p][pq] - mx); s += att[p][pq]; }
            float inv = 1.0f / s;
#pragma unroll
            for (int pq = 0; pq < 4; ++pq) att[p][pq] *= inv;
        }
    }
    stage_wpre(bHi, bLo, 2, tid);
    __syncthreads();                                        // (5)

    // ===== V GEMM =====
    GEMM64(EPI_CF)
    __syncthreads();                                        // (6)

    // mid C: o = att*v -> A (exclusive slots); restage B <- wp
    {
#pragma unroll
        for (int j = 0; j < 8; ++j) {
            int c = h * 8 + j;
            float vv[4];
#pragma unroll
            for (int p = 0; p < 4; ++p) vv[p] = Cf[(t * 4 + p) * 68 + c];
#pragma unroll
            for (int p = 0; p < 4; ++p) {
                float o = att[p][0] * vv[0] + att[p][1] * vv[1] +
                          att[p][2] * vv[2] + att[p][3] * vv[3];
                __nv_bfloat16 hh, ll;
                bsplit(o, hh, ll);
                int row = t * 4 + p;
                aHi[row * 72 + c] = hh;
                aLo[row * 72 + c] = ll;
            }
        }
    }
    stage_wpre(bHi, bLo, 3, tid);
    __syncthreads();                                        // (7)

    // ===== P GEMM -> out staging =====
#define EPI_OUT                                                                 \
        _Pragma("unroll")                                                       \
        for (int mt = 0; mt < 2; ++mt)                                          \
            _Pragma("unroll")                                                   \
            for (int nb = 0; nb < 4; ++nb) {                                    \
                int row = row0 + mt * 16 + gid;                                 \
                int col = col0 + nb * 8 + 2 * tig;                              \
                int tt = row >> 2, p = row & 3;                                 \
                out_s[(p * 64 + col) * 16 + tt]         = acc[mt][nb][0] + sb[col]; \
                out_s[(p * 64 + col + 1) * 16 + tt]     = acc[mt][nb][1] + sb[col + 1]; \
                out_s[(p * 64 + col) * 16 + tt + 2]     = acc[mt][nb][2] + sb[col]; \
                out_s[(p * 64 + col + 1) * 16 + tt + 2] = acc[mt][nb][3] + sb[col + 1]; \
            }

    GEMM64(EPI_OUT)
    __syncthreads();                                        // (8)

    // coalesced writeback (16-token rows = 64B segments)
    for (int i4 = tid; i4 < 1024; i4 += 128) {
        int pc = i4 >> 2;
        int t4 = (i4 & 3) * 4;
        int p = pc >> 6, c = pc & 63;
        float4 vv = *(const float4*)(out_s + pc * 16 + t4);
        *(float4*)(out + (size_t)((b * 4 + p) * 64 + c) * HW + pos0 + t4) = vv;
    }
}

// ---------------------------------------------------------------------------
extern "C" void kernel_launch(void* const* d_in, const int* in_sizes, int n_in,
                              void* d_out, int out_size) {
    (void)in_sizes; (void)n_in; (void)out_size;
    const float* x_in   = (const float*)d_in[0];
    const float* mask   = (const float*)d_in[1];
    const float* wq     = (const float*)d_in[2];
    const float* wk     = (const float*)d_in[3];
    const float* wv     = (const float*)d_in[4];
    const float* w_proj = (const float*)d_in[5];
    const float* b_proj = (const float*)d_in[6];
    const float* rescale= (const float*)d_in[7];
    const float* dw_w   = (const float*)d_in[8];
    const float* dw_b   = (const float*)d_in[9];
    const float* pw_w   = (const float*)d_in[10];
    const float* pw_b   = (const float*)d_in[11];
    float* out = (float*)d_out;

    cudaFuncSetAttribute(attn_fused, cudaFuncAttributeMaxDynamicSharedMemorySize,
                         ATTN_SMEM_BYTES);

    mask_kernel3<<<dim3(8, 16), 256>>>(mask, dw_w, dw_b, pw_w, pw_b,
                                       wq, wk, wv, w_proj);
    attn_fused<<<dim3(1024, Bn), 128, ATTN_SMEM_BYTES>>>(
        x_in, b_proj, rescale, out);
}

// round 15
// speedup vs baseline: 2.2389x; 1.0276x over previous
#include <cuda_runtime.h>
#include <cuda_bf16.h>
#include <math.h>

#define Bn 4
#define Pp 4
#define Cc 64
#define NH 8
#define Hh 128
#define Wd 128
#define HW 16384

// scratch (no cudaMalloc allowed)
__device__ float g_mb[16 * HW];                 // mask bias per (b,p,pos)
__device__ __nv_bfloat16 g_wHi[4][4096];        // pre-split weights hi
__device__ __nv_bfloat16 g_wLo[4][4096];        // pre-split weights lo

// ---------------------------------------------------------------------------
// helpers
// ---------------------------------------------------------------------------
__device__ __forceinline__ void bsplit(float f, __nv_bfloat16& h, __nv_bfloat16& l) {
    h = __float2bfloat16(f);
    l = __float2bfloat16(f - __bfloat162float(h));
}

__device__ __forceinline__ void mma16816(float* c, const unsigned* a,
                                         unsigned b0, unsigned b1) {
    asm volatile(
        "mma.sync.aligned.m16n8k16.row.col.f32.bf16.bf16.f32 "
        "{%0,%1,%2,%3}, {%4,%5,%6,%7}, {%8,%9}, {%0,%1,%2,%3};"
        : "+f"(c[0]), "+f"(c[1]), "+f"(c[2]), "+f"(c[3])
        : "r"(a[0]), "r"(a[1]), "r"(a[2]), "r"(a[3]), "r"(b0), "r"(b1));
}

// ---------------------------------------------------------------------------
// Kernel 1: mask branch (R13, known-good ~55us) + folded weight pre-split.
// ---------------------------------------------------------------------------
#define TS (18 * 132)
__global__ void __launch_bounds__(256)
mask_kernel3(const float* __restrict__ mask,
             const float* __restrict__ dw_w,
             const float* __restrict__ dw_b,
             const float* __restrict__ pw_w,
             const float* __restrict__ pw_b,
             const float* __restrict__ wq,
             const float* __restrict__ wk,
             const float* __restrict__ wv,
             const float* __restrict__ wp) {
    __shared__ float tilef[4 * TS];
    __shared__ float sdw[Cc][9];
    __shared__ float sdb[Cc];
    __shared__ float swbar[Cc + 1];
    __shared__ float wpart[4][Cc];

    int tid = threadIdx.x;
    int h0 = blockIdx.x * 16;
    int bp = blockIdx.y;

    if (blockIdx.x == 0) {
        int i = bp * 256 + tid;
        const float* Ws[4] = {wq, wk, wv, wp};
#pragma unroll
        for (int m = 0; m < 4; ++m) {
            __nv_bfloat16 h, l;
            bsplit(Ws[m][i], h, l);
            g_wHi[m][i] = h;
            g_wLo[m][i] = l;
        }
    }

    for (int i = tid; i < Cc * 9; i += 256) sdw[i / 9][i % 9] = dw_w[i];
    for (int i = tid; i < Cc; i += 256) sdb[i] = dw_b[i];
    {
        int c = tid & 63, dg = tid >> 6;
        float s = 0.f;
        for (int d = dg * 16; d < dg * 16 + 16; ++d) s += pw_w[d * Cc + c];
        wpart[dg][c] = s;
    }
    if (tid >= 192 && tid < 224) {
        float s = pw_b[tid - 192] + pw_b[tid - 192 + 32];
#pragma unroll
        for (int o = 16; o > 0; o >>= 1)
            s += __shfl_down_sync(0xFFFFFFFFu, s, o);
        if (tid == 192) swbar[Cc] = s * (1.0f / Cc);
    }
    if (tid < 72) {
        int cc = tid / 18, r = tid % 18;
        tilef[cc * TS + r * 132 + 0] = 0.f;
        tilef[cc * TS + r * 132 + 129] = 0.f;
    }
    __syncthreads();
    if (tid < Cc)
        swbar[tid] = (wpart[0][tid] + wpart[1][tid] + wpart[2][tid] + wpart[3][tid]) * (1.0f / Cc);

    const int col = tid & 127;
    const int rowgrp = tid >> 7;
    const float* base = mask + (size_t)bp * Cc * HW;

    float acc[8];
#pragma unroll
    for (int j = 0; j < 8; ++j) acc[j] = 0.f;

    for (int cb = 0; cb < Cc; cb += 4) {
        __syncthreads();
#pragma unroll
        for (int it = 0; it < 9; ++it) {
            int r = it * 2 + rowgrp;
            int gh = h0 + r - 1;
            bool ok = (gh >= 0 && gh < Hh);
            const float* src = base + (size_t)cb * HW + gh * Wd + col;
            float* dst = tilef + r * 132 + col + 1;
#pragma unroll
            for (int cc = 0; cc < 4; ++cc)
                dst[cc * TS] = ok ? src[(size_t)cc * HW] : 0.f;
        }
        __syncthreads();
#pragma unroll
        for (int cc = 0; cc < 4; ++cc) {
            int c = cb + cc;
            const float* tb = tilef + cc * TS + col;
            float w0 = sdw[c][0], w1 = sdw[c][1], w2 = sdw[c][2];
            float w3 = sdw[c][3], w4 = sdw[c][4], w5 = sdw[c][5];
            float w6 = sdw[c][6], w7 = sdw[c][7], w8 = sdw[c][8];
            float bias = sdb[c], wb = swbar[c];
#pragma unroll
            for (int j = 0; j < 8; ++j) {
                int lr = rowgrp * 8 + j;
                const float* t0 = tb + lr * 132;
                float y = bias
                    + t0[0] * w0 + t0[1] * w1 + t0[2] * w2
                    + t0[132] * w3 + t0[133] * w4 + t0[134] * w5
                    + t0[264] * w6 + t0[265] * w7 + t0[266] * w8;
                float g = 0.5f * y * (1.0f + erff(y * 0.70710678118654752f));
                acc[j] += wb * g;
            }
        }
    }
    float bb = swbar[Cc];
#pragma unroll
    for (int j = 0; j < 8; ++j) {
        int lr = rowgrp * 8 + j;
        g_mb[(size_t)bp * HW + (h0 + lr) * Wd + col] = acc[j] + bb;
    }
}

// ---------------------------------------------------------------------------
// Kernel 2: fused 16-token tile, 128 threads, 4 CTAs/SM.
// A/B in SW128-swizzled 128B rows -> conflict-free fragment LDS.
// smem byte offsets:
//   aHi @0 (64x128B=8192), aLo @8192
//   bHi @16384 (8192), bLo @24576         wq -> wk -> wv -> wp
//   Cf fp32 @32768, 64x68 = 17408B
//   mb_s[64] sb[64] sr[8] after Cf
// total = 50720 B -> 4 CTAs/SM
// ---------------------------------------------------------------------------
#define SM_AHI 0
#define SM_ALO 8192
#define SM_BHI 16384
#define SM_BLO 24576
#define SM_CF  32768
#define ATTN_SMEM_BYTES 50720

// swizzled byte offset within a 64-row x 128B tile
#define SWZ(row, colb) ((row) * 128 + ((colb) ^ (((row) & 7) * 16)))

__device__ __forceinline__ void stage_wpre(char* dHi, char* dLo, int m, int tid) {
    const uint4* sHi = (const uint4*)g_wHi[m];
    const uint4* sLo = (const uint4*)g_wLo[m];
#pragma unroll
    for (int s = 0; s < 4; ++s) {
        int i8 = tid + s * 128;          // 512 groups of 8 bf16 (16B)
        int n = i8 >> 3, cb = (i8 & 7) * 16;
        unsigned off = SWZ(n, cb);
        *(uint4*)(dHi + off) = sHi[i8];
        *(uint4*)(dLo + off) = sLo[i8];
    }
}

__global__ void __launch_bounds__(128, 4)
attn_fused(const float* __restrict__ x_in,
           const float* __restrict__ b_proj,
           const float* __restrict__ rescale,
           float* __restrict__ out) {
    extern __shared__ char smem[];
    char* aHi = smem + SM_AHI;
    char* aLo = smem + SM_ALO;
    char* bHi = smem + SM_BHI;
    char* bLo = smem + SM_BLO;
    float* Cf    = (float*)(smem + SM_CF);
    float* mb_s  = Cf + 4352;
    float* sb    = mb_s + 64;
    float* sr    = sb + 64;
    float* out_s = Cf;

    int tid = threadIdx.x;
    int b = blockIdx.y;
    int pos0 = blockIdx.x * 16;

    // stage B = wq
    stage_wpre(bHi, bLo, 0, tid);
    // stage A: batch 8 LDG.128, then convert; rows = t*4+p
    {
        float4 xr[8];
#pragma unroll
        for (int s = 0; s < 8; ++s) {
            int i4 = tid + s * 128;
            int pc = i4 >> 2;
            int t4 = (i4 & 3) * 4;
            int p = pc >> 6, c = pc & 63;
            xr[s] = *(const float4*)(x_in + (size_t)((b * 4 + p) * 64 + c) * HW + pos0 + t4);
        }
#pragma unroll
        for (int s = 0; s < 8; ++s) {
            int i4 = tid + s * 128;
            int pc = i4 >> 2;
            int t4 = (i4 & 3) * 4;
            int p = pc >> 6, c = pc & 63;
            float xs[4] = {xr[s].x, xr[s].y, xr[s].z, xr[s].w};
#pragma unroll
            for (int j = 0; j < 4; ++j) {
                int row = (t4 + j) * 4 + p;
                __nv_bfloat16 hh, ll;
                bsplit(xs[j], hh, ll);
                unsigned off = SWZ(row, c * 2);
                *(__nv_bfloat16*)(aHi + off) = hh;
                *(__nv_bfloat16*)(aLo + off) = ll;
            }
        }
    }
    if (tid < 64) {
        int p = tid >> 4, t = tid & 15;
        mb_s[t * 4 + p] = g_mb[(size_t)(b * 4 + p) * HW + pos0 + t];
        sb[tid] = b_proj[tid];
    }
    if (tid < 8) sr[tid] = rescale[tid];
    __syncthreads();                                        // (1)

    int lane = tid & 31, wid = tid >> 5;
    int gid = lane >> 2, tig = lane & 3;
    const int t = tid >> 3, h = tid & 7;
    int wm = wid & 1, wn = wid >> 1;
    int row0 = wm * 32, col0 = wn * 32;
    const unsigned xorv = (unsigned)(gid * 16);

#define GEMM64(EPILOG)                                                          \
    {                                                                           \
        float acc[2][4][4];                                                     \
        _Pragma("unroll")                                                       \
        for (int mt = 0; mt < 2; ++mt)                                          \
            _Pragma("unroll")                                                   \
            for (int nb = 0; nb < 4; ++nb)                                      \
                _Pragma("unroll")                                               \
                for (int i = 0; i < 4; ++i) acc[mt][nb][i] = 0.f;               \
        _Pragma("unroll")                                                       \
        for (int kk = 0; kk < 4; ++kk) {                                        \
            unsigned k0 = (unsigned)(kk * 32 + 4 * tig);                        \
            unsigned c0 = k0 ^ xorv;                                            \
            unsigned c1 = (k0 + 16) ^ xorv;                                     \
            unsigned aH[2][4], aL[2][4];                                        \
            _Pragma("unroll")                                                   \
            for (int mt = 0; mt < 2; ++mt) {                                    \
                unsigned rb = (unsigned)((row0 + mt * 16 + gid) * 128);         \
                aH[mt][0] = *(const unsigned*)(aHi + rb + c0);                  \
                aH[mt][1] = *(const unsigned*)(aHi + rb + 1024 + c0);           \
                aH[mt][2] = *(const unsigned*)(aHi + rb + c1);                  \
                aH[mt][3] = *(const unsigned*)(aHi + rb + 1024 + c1);           \
                aL[mt][0] = *(const unsigned*)(aLo + rb + c0);                  \
                aL[mt][1] = *(const unsigned*)(aLo + rb + 1024 + c0);           \
                aL[mt][2] = *(const unsigned*)(aLo + rb + c1);                  \
                aL[mt][3] = *(const unsigned*)(aLo + rb + 1024 + c1);           \
            }                                                                   \
            _Pragma("unroll")                                                   \
            for (int nb = 0; nb < 4; ++nb) {                                    \
                unsigned nb_ = (unsigned)((col0 + nb * 8 + gid) * 128);         \
                unsigned bh0 = *(const unsigned*)(bHi + nb_ + c0);              \
                unsigned bh1 = *(const unsigned*)(bHi + nb_ + c1);              \
                unsigned bl0 = *(const unsigned*)(bLo + nb_ + c0);              \
                unsigned bl1 = *(const unsigned*)(bLo + nb_ + c1);              \
                _Pragma("unroll")                                               \
                for (int mt = 0; mt < 2; ++mt) {                                \
                    mma16816(acc[mt][nb], aH[mt], bh0, bh1);                    \
                    mma16816(acc[mt][nb], aH[mt], bl0, bl1);                    \
                    mma16816(acc[mt][nb], aL[mt], bh0, bh1);                    \
                }                                                               \
            }                                                                   \
        }                                                                       \
        EPILOG                                                                  \
    }

#define EPI_CF                                                                  \
        _Pragma("unroll")                                                       \
        for (int mt = 0; mt < 2; ++mt)                                          \
            _Pragma("unroll")                                                   \
            for (int nb = 0; nb < 4; ++nb) {                                    \
                int row = row0 + mt * 16 + gid;                                 \
                int col = col0 + nb * 8 + 2 * tig;                              \
                float* dst = Cf + row * 68 + col;                               \
                *(float2*)dst = make_float2(acc[mt][nb][0], acc[mt][nb][1]);    \
                *(float2*)(dst + 8 * 68) = make_float2(acc[mt][nb][2], acc[mt][nb][3]); \
            }

    // ===== Q GEMM =====
    GEMM64(EPI_CF)
    __syncthreads();                                        // (2)

    // mid A: read q -> regs; restage B <- wk
    float q[4][8];
#pragma unroll
    for (int p = 0; p < 4; ++p) {
        const float* cr = Cf + (t * 4 + p) * 68 + h * 8;
#pragma unroll
        for (int j2 = 0; j2 < 4; ++j2) {
            float2 qq = *(const float2*)(cr + 2 * j2);
            q[p][2 * j2] = qq.x; q[p][2 * j2 + 1] = qq.y;
        }
    }
    stage_wpre(bHi, bLo, 1, tid);
    __syncthreads();                                        // (3)

    // ===== K GEMM =====
    GEMM64(EPI_CF)
    __syncthreads();                                        // (4)

    // mid B: read k, normalize, softmax -> att; restage B <- wv
    float att[4][4];
    {
        float k[4][8];
#pragma unroll
        for (int p = 0; p < 4; ++p) {
            const float* cr = Cf + (t * 4 + p) * 68 + h * 8;
#pragma unroll
            for (int j2 = 0; j2 < 4; ++j2) {
                float2 kk2 = *(const float2*)(cr + 2 * j2);
                k[p][2 * j2] = kk2.x; k[p][2 * j2 + 1] = kk2.y;
            }
        }
#pragma unroll
        for (int p = 0; p < 4; ++p) {
            float sq = 0.f, sk = 0.f;
#pragma unroll
            for (int j = 0; j < 8; ++j) { sq += q[p][j] * q[p][j]; sk += k[p][j] * k[p][j]; }
            float iq = 1.0f / fmaxf(sqrtf(sq), 1e-12f);
            float ik = 1.0f / fmaxf(sqrtf(sk), 1e-12f);
#pragma unroll
            for (int j = 0; j < 8; ++j) { q[p][j] *= iq; k[p][j] *= ik; }
        }
        float rh = sr[h];
        float mbl[4];
#pragma unroll
        for (int p = 0; p < 4; ++p) mbl[p] = mb_s[t * 4 + p];
#pragma unroll
        for (int p = 0; p < 4; ++p) {
#pragma unroll
            for (int pq = 0; pq < 4; ++pq) {
                float d = 0.f;
#pragma unroll
                for (int j = 0; j < 8; ++j) d += q[p][j] * k[pq][j];
                att[p][pq] = d * rh + (mbl[pq] - mbl[p]);
            }
            float mx = fmaxf(fmaxf(att[p][0], att[p][1]), fmaxf(att[p][2], att[p][3]));
            float s = 0.f;
#pragma unroll
            for (int pq = 0; pq < 4; ++pq) { att[p][pq] = __expf(att[p][pq] - mx); s += att[p][pq]; }
            float inv = 1.0f / s;
#pragma unroll
            for (int pq = 0; pq < 4; ++pq) att[p][pq] *= inv;
        }
    }
    stage_wpre(bHi, bLo, 2, tid);
    __syncthreads();                                        // (5)

    // ===== V GEMM =====
    GEMM64(EPI_CF)
    __syncthreads();                                        // (6)

    // mid C: o = att*v -> A (exclusive slots); restage B <- wp
    {
#pragma unroll
        for (int j = 0; j < 8; ++j) {
            int c = h * 8 + j;
            float vv[4];
#pragma unroll
            for (int p = 0; p < 4; ++p) vv[p] = Cf[(t * 4 + p) * 68 + c];
#pragma unroll
            for (int p = 0; p < 4; ++p) {
                float o = att[p][0] * vv[0] + att[p][1] * vv[1] +
                          att[p][2] * vv[2] + att[p][3] * vv[3];
                __nv_bfloat16 hh, ll;
                bsplit(o, hh, ll);
                int row = t * 4 + p;
                unsigned off = SWZ(row, c * 2);
                *(__nv_bfloat16*)(aHi + off) = hh;
                *(__nv_bfloat16*)(aLo + off) = ll;
            }
        }
    }
    stage_wpre(bHi, bLo, 3, tid);
    __syncthreads();                                        // (7)

    // ===== P GEMM -> out staging =====
#define EPI_OUT                                                                 \
        _Pragma("unroll")                                                       \
        for (int mt = 0; mt < 2; ++mt)                                          \
            _Pragma("unroll")                                                   \
            for (int nb = 0; nb < 4; ++nb) {                                    \
                int row = row0 + mt * 16 + gid;                                 \
                int col = col0 + nb * 8 + 2 * tig;                              \
                int tt = row >> 2, p = row & 3;                                 \
                out_s[(p * 64 + col) * 16 + tt]         = acc[mt][nb][0] + sb[col]; \
                out_s[(p * 64 + col + 1) * 16 + tt]     = acc[mt][nb][1] + sb[col + 1]; \
                out_s[(p * 64 + col) * 16 + tt + 2]     = acc[mt][nb][2] + sb[col]; \
                out_s[(p * 64 + col + 1) * 16 + tt + 2] = acc[mt][nb][3] + sb[col + 1]; \
            }

    GEMM64(EPI_OUT)
    __syncthreads();                                        // (8)

    // coalesced writeback (16-token rows = 64B segments)
    for (int i4 = tid; i4 < 1024; i4 += 128) {
        int pc = i4 >> 2;
        int t4 = (i4 & 3) * 4;
        int p = pc >> 6, c = pc & 63;
        float4 vv = *(const float4*)(out_s + pc * 16 + t4);
        *(float4*)(out + (size_t)((b * 4 + p) * 64 + c) * HW + pos0 + t4) = vv;
    }
}

// ---------------------------------------------------------------------------
extern "C" void kernel_launch(void* const* d_in, const int* in_sizes, int n_in,
                              void* d_out, int out_size) {
    (void)in_sizes; (void)n_in; (void)out_size;
    const float* x_in   = (const float*)d_in[0];
    const float* mask   = (const float*)d_in[1];
    const float* wq     = (const float*)d_in[2];
    const float* wk     = (const float*)d_in[3];
    const float* wv     = (const float*)d_in[4];
    const float* w_proj = (const float*)d_in[5];
    const float* b_proj = (const float*)d_in[6];
    const float* rescale= (const float*)d_in[7];
    const float* dw_w   = (const float*)d_in[8];
    const float* dw_b   = (const float*)d_in[9];
    const float* pw_w   = (const float*)d_in[10];
    const float* pw_b   = (const float*)d_in[11];
    float* out = (float*)d_out;

    cudaFuncSetAttribute(attn_fused, cudaFuncAttributeMaxDynamicSharedMemorySize,
                         ATTN_SMEM_BYTES);

    mask_kernel3<<<dim3(8, 16), 256>>>(mask, dw_w, dw_b, pw_w, pw_b,
                                       wq, wk, wv, w_proj);
    attn_fused<<<dim3(1024, Bn), 128, ATTN_SMEM_BYTES>>>(
        x_in, b_proj, rescale, out);
}

// round 16
// speedup vs baseline: 2.2454x; 1.0029x over previous
#include <cuda_runtime.h>
#include <cuda_bf16.h>
#include <math.h>

#define Bn 4
#define Pp 4
#define Cc 64
#define NH 8
#define Hh 128
#define Wd 128
#define HW 16384

// scratch (no cudaMalloc allowed)
__device__ float g_mb[16 * HW];          // mask bias per (b,p,pos)
__device__ uint4 g_wFrag[4096];          // 4 matrices x 1024 fragment-quads (16KB each)

// ---------------------------------------------------------------------------
// helpers
// ---------------------------------------------------------------------------
__device__ __forceinline__ unsigned short bhi(float f) {
    return __bfloat16_as_ushort(__float2bfloat16(f));
}
__device__ __forceinline__ void bsplit2(float f, unsigned short& h, unsigned short& l) {
    __nv_bfloat16 hb = __float2bfloat16(f);
    h = __bfloat16_as_ushort(hb);
    l = __bfloat16_as_ushort(__float2bfloat16(f - __bfloat162float(hb)));
}

__device__ __forceinline__ void mma16816(float* c, const unsigned* a,
                                         unsigned b0, unsigned b1) {
    asm volatile(
        "mma.sync.aligned.m16n8k16.row.col.f32.bf16.bf16.f32 "
        "{%0,%1,%2,%3}, {%4,%5,%6,%7}, {%8,%9}, {%0,%1,%2,%3};"
        : "+f"(c[0]), "+f"(c[1]), "+f"(c[2]), "+f"(c[3])
        : "r"(a[0]), "r"(a[1]), "r"(a[2]), "r"(a[3]), "r"(b0), "r"(b1));
}

// fragment-order byte offset for element (row, col) in a 64x64 A tile.
// quad layout: block = rowgrp*8 + kk*2 + mt (16 blocks of 512B), lane = gid8*4+tig,
// slot = half + 2*colhalf, then (col&1)*2 within the 4B granule.
__device__ __forceinline__ unsigned a_addr(int row, int col) {
    int rowgrp = row >> 5, mt = (row >> 4) & 1, gid8 = row & 7, half = (row >> 3) & 1;
    int kk = col >> 4, colhalf = (col >> 3) & 1, tig = (col >> 1) & 3;
    return (unsigned)(((rowgrp * 8 + kk * 2 + mt) * 32 + gid8 * 4 + tig) * 16
                      + (half + 2 * colhalf) * 4 + (col & 1) * 2);
}

// ---------------------------------------------------------------------------
// Kernel 1: mask branch (row-band) + weight fragment-quad precompute.
// 8 channels per barrier round.
// ---------------------------------------------------------------------------
#define TS (18 * 132)
__global__ void __launch_bounds__(256)
mask_kernel3(const float* __restrict__ mask,
             const float* __restrict__ dw_w,
             const float* __restrict__ dw_b,
             const float* __restrict__ pw_w,
             const float* __restrict__ pw_b,
             const float* __restrict__ wq,
             const float* __restrict__ wk,
             const float* __restrict__ wv,
             const float* __restrict__ wp) {
    __shared__ float tilef[8 * TS];
    __shared__ float sdw[Cc][9];
    __shared__ float sdb[Cc];
    __shared__ float swbar[Cc + 1];
    __shared__ float wpart[4][Cc];

    int tid = threadIdx.x;
    int h0 = blockIdx.x * 16;
    int bp = blockIdx.y;

    // weight fragment precompute: 16 blocks (blockIdx.x==0) x 256 thr = 4096 quads
    if (blockIdx.x == 0) {
        int qi = bp * 256 + tid;
        int m = qi >> 10, r = qi & 1023;
        int colgrp = r >> 9, kk = (r >> 7) & 3, nb = (r >> 5) & 3, lane = r & 31;
        int gid = lane >> 2, tig = lane & 3;
        int n = colgrp * 32 + nb * 8 + gid;
        int k0 = kk * 16 + 2 * tig;
        const float* Ws[4] = {wq, wk, wv, wp};
        const float* W = Ws[m];
        float w00 = W[n * 64 + k0],     w01 = W[n * 64 + k0 + 1];
        float w10 = W[n * 64 + k0 + 8], w11 = W[n * 64 + k0 + 9];
        unsigned short h00, l00, h01, l01, h10, l10, h11, l11;
        bsplit2(w00, h00, l00); bsplit2(w01, h01, l01);
        bsplit2(w10, h10, l10); bsplit2(w11, h11, l11);
        uint4 v;
        v.x = (unsigned)h00 | ((unsigned)h01 << 16);
        v.y = (unsigned)h10 | ((unsigned)h11 << 16);
        v.z = (unsigned)l00 | ((unsigned)l01 << 16);
        v.w = (unsigned)l10 | ((unsigned)l11 << 16);
        g_wFrag[m * 1024 + (colgrp * 16 + kk * 4 + nb) * 32 + lane] = v;
    }

    for (int i = tid; i < Cc * 9; i += 256) sdw[i / 9][i % 9] = dw_w[i];
    for (int i = tid; i < Cc; i += 256) sdb[i] = dw_b[i];
    {
        int c = tid & 63, dg = tid >> 6;
        float s = 0.f;
        for (int d = dg * 16; d < dg * 16 + 16; ++d) s += pw_w[d * Cc + c];
        wpart[dg][c] = s;
    }
    if (tid >= 192 && tid < 224) {
        float s = pw_b[tid - 192] + pw_b[tid - 192 + 32];
#pragma unroll
        for (int o = 16; o > 0; o >>= 1)
            s += __shfl_down_sync(0xFFFFFFFFu, s, o);
        if (tid == 192) swbar[Cc] = s * (1.0f / Cc);
    }
    if (tid < 144) {
        int cc = tid / 18, r = tid % 18;
        tilef[cc * TS + r * 132 + 0] = 0.f;
        tilef[cc * TS + r * 132 + 129] = 0.f;
    }
    __syncthreads();
    if (tid < Cc)
        swbar[tid] = (wpart[0][tid] + wpart[1][tid] + wpart[2][tid] + wpart[3][tid]) * (1.0f / Cc);

    const int col = tid & 127;
    const int rowgrp = tid >> 7;
    const float* base = mask + (size_t)bp * Cc * HW;

    float acc[8];
#pragma unroll
    for (int j = 0; j < 8; ++j) acc[j] = 0.f;

    for (int cb = 0; cb < Cc; cb += 8) {
        __syncthreads();
#pragma unroll
        for (int it = 0; it < 9; ++it) {
            int r = it * 2 + rowgrp;
            int gh = h0 + r - 1;
            bool ok = (gh >= 0 && gh < Hh);
            const float* src = base + (size_t)cb * HW + gh * Wd + col;
            float* dst = tilef + r * 132 + col + 1;
#pragma unroll
            for (int cc = 0; cc < 8; ++cc)
                dst[cc * TS] = ok ? src[(size_t)cc * HW] : 0.f;
        }
        __syncthreads();
#pragma unroll
        for (int cc = 0; cc < 8; ++cc) {
            int c = cb + cc;
            const float* tb = tilef + cc * TS + col;
            float w0 = sdw[c][0], w1 = sdw[c][1], w2 = sdw[c][2];
            float w3 = sdw[c][3], w4 = sdw[c][4], w5 = sdw[c][5];
            float w6 = sdw[c][6], w7 = sdw[c][7], w8 = sdw[c][8];
            float bias = sdb[c], wb = swbar[c];
#pragma unroll
            for (int j = 0; j < 8; ++j) {
                int lr = rowgrp * 8 + j;
                const float* t0 = tb + lr * 132;
                float y = bias
                    + t0[0] * w0 + t0[1] * w1 + t0[2] * w2
                    + t0[132] * w3 + t0[133] * w4 + t0[134] * w5
                    + t0[264] * w6 + t0[265] * w7 + t0[266] * w8;
                float g = 0.5f * y * (1.0f + erff(y * 0.70710678118654752f));
                acc[j] += wb * g;
            }
        }
    }
    float bb = swbar[Cc];
#pragma unroll
    for (int j = 0; j < 8; ++j) {
        int lr = rowgrp * 8 + j;
        g_mb[(size_t)bp * HW + (h0 + lr) * Wd + col] = acc[j] + bb;
    }
}

// ---------------------------------------------------------------------------
// Kernel 2: fused 16-token tile, 128 thr, 4 CTAs/SM.
// A/B in FRAGMENT ORDER -> LDS.128 fragment loads (4x fewer LDS instructions).
// smem: aHi @0 (8KB), aLo @8192, Bq @16384 (16KB quads), Cf fp32 @32768 (17408),
//       mb/sb/sr after. total = 50720 B.
// ---------------------------------------------------------------------------
#define SM_AHI 0
#define SM_ALO 8192
#define SM_BQ  16384
#define SM_CF  32768
#define ATTN_SMEM_BYTES 50720

__global__ void __launch_bounds__(128, 4)
attn_fused(const float* __restrict__ x_in,
           const float* __restrict__ b_proj,
           const float* __restrict__ rescale,
           float* __restrict__ out) {
    extern __shared__ char smem[];
    char* aHi = smem + SM_AHI;
    char* aLo = smem + SM_ALO;
    uint4* Bq = (uint4*)(smem + SM_BQ);
    float* Cf    = (float*)(smem + SM_CF);
    float* mb_s  = Cf + 4352;
    float* sb    = mb_s + 64;
    float* sr    = sb + 64;
    float* out_s = Cf;

    int tid = threadIdx.x;
    int b = blockIdx.y;
    int pos0 = blockIdx.x * 16;

    // stage B = wq fragment quads (flat copy)
    {
        const uint4* src = g_wFrag;
#pragma unroll
        for (int s = 0; s < 8; ++s) Bq[tid + s * 128] = src[tid + s * 128];
    }
    // stage A: batch 8 LDG.128, then bsplit into fragment-order
    {
        float4 xr[8];
#pragma unroll
        for (int s = 0; s < 8; ++s) {
            int i4 = tid + s * 128;
            int pc = i4 >> 2;
            int t4 = (i4 & 3) * 4;
            int p = pc >> 6, c = pc & 63;
            xr[s] = *(const float4*)(x_in + (size_t)((b * 4 + p) * 64 + c) * HW + pos0 + t4);
        }
#pragma unroll
        for (int s = 0; s < 8; ++s) {
            int i4 = tid + s * 128;
            int pc = i4 >> 2;
            int t4 = (i4 & 3) * 4;
            int p = pc >> 6, c = pc & 63;
            float xs[4] = {xr[s].x, xr[s].y, xr[s].z, xr[s].w};
#pragma unroll
            for (int j = 0; j < 4; ++j) {
                int row = (t4 + j) * 4 + p;
                unsigned short hh, ll;
                bsplit2(xs[j], hh, ll);
                unsigned off = a_addr(row, c);
                *(unsigned short*)(aHi + off) = hh;
                *(unsigned short*)(aLo + off) = ll;
            }
        }
    }
    if (tid < 64) {
        int p = tid >> 4, t = tid & 15;
        mb_s[t * 4 + p] = g_mb[(size_t)(b * 4 + p) * HW + pos0 + t];
        sb[tid] = b_proj[tid];
    }
    if (tid < 8) sr[tid] = rescale[tid];
    __syncthreads();                                        // (1)

    int lane = tid & 31, wid = tid >> 5;
    int gid = lane >> 2, tig = lane & 3;
    const int t = tid >> 3, h = tid & 7;
    int wm = wid & 1, wn = wid >> 1;
    int row0 = wm * 32, col0 = wn * 32;

#define GEMM64(EPILOG)                                                          \
    {                                                                           \
        float acc[2][4][4];                                                     \
        _Pragma("unroll")                                                       \
        for (int mt = 0; mt < 2; ++mt)                                          \
            _Pragma("unroll")                                                   \
            for (int nb = 0; nb < 4; ++nb)                                      \
                _Pragma("unroll")                                               \
                for (int i = 0; i < 4; ++i) acc[mt][nb][i] = 0.f;               \
        _Pragma("unroll")                                                       \
        for (int kk = 0; kk < 4; ++kk) {                                        \
            uint4 vh[2], vl[2];                                                 \
            _Pragma("unroll")                                                   \
            for (int mt = 0; mt < 2; ++mt) {                                    \
                unsigned ao = (unsigned)(((wm * 8 + kk * 2 + mt) * 32 + lane) * 16); \
                vh[mt] = *(const uint4*)(aHi + ao);                             \
                vl[mt] = *(const uint4*)(aLo + ao);                             \
            }                                                                   \
            _Pragma("unroll")                                                   \
            for (int nb = 0; nb < 4; ++nb) {                                    \
                uint4 bb = Bq[(wn * 16 + kk * 4 + nb) * 32 + lane];             \
                _Pragma("unroll")                                               \
                for (int mt = 0; mt < 2; ++mt) {                                \
                    mma16816(acc[mt][nb], (const unsigned*)&vh[mt], bb.x, bb.y);\
                    mma16816(acc[mt][nb], (const unsigned*)&vh[mt], bb.z, bb.w);\
                    mma16816(acc[mt][nb], (const unsigned*)&vl[mt], bb.x, bb.y);\
                }                                                               \
            }                                                                   \
        }                                                                       \
        EPILOG                                                                  \
    }

#define EPI_CF                                                                  \
        _Pragma("unroll")                                                       \
        for (int mt = 0; mt < 2; ++mt)                                          \
            _Pragma("unroll")                                                   \
            for (int nb = 0; nb < 4; ++nb) {                                    \
                int row = row0 + mt * 16 + gid;                                 \
                int col = col0 + nb * 8 + 2 * tig;                              \
                float* dst = Cf + row * 68 + col;                               \
                *(float2*)dst = make_float2(acc[mt][nb][0], acc[mt][nb][1]);    \
                *(float2*)(dst + 8 * 68) = make_float2(acc[mt][nb][2], acc[mt][nb][3]); \
            }

#define STAGE_B(m)                                                              \
    {                                                                           \
        const uint4* src = g_wFrag + (m) * 1024;                                \
        _Pragma("unroll")                                                       \
        for (int s = 0; s < 8; ++s) Bq[tid + s * 128] = src[tid + s * 128];     \
    }

    // ===== Q GEMM =====
    GEMM64(EPI_CF)
    __syncthreads();                                        // (2)

    // mid A: read q -> regs; restage B <- wk
    float q[4][8];
#pragma unroll
    for (int p = 0; p < 4; ++p) {
        const float4* cr = (const float4*)(Cf + (t * 4 + p) * 68 + h * 8);
        float4 a0 = cr[0], a1 = cr[1];
        q[p][0] = a0.x; q[p][1] = a0.y; q[p][2] = a0.z; q[p][3] = a0.w;
        q[p][4] = a1.x; q[p][5] = a1.y; q[p][6] = a1.z; q[p][7] = a1.w;
    }
    STAGE_B(1)
    __syncthreads();                                        // (3)

    // ===== K GEMM =====
    GEMM64(EPI_CF)
    __syncthreads();                                        // (4)

    // mid B: read k, normalize, softmax -> att; restage B <- wv
    float att[4][4];
    {
        float k[4][8];
#pragma unroll
        for (int p = 0; p < 4; ++p) {
            const float4* cr = (const float4*)(Cf + (t * 4 + p) * 68 + h * 8);
            float4 a0 = cr[0], a1 = cr[1];
            k[p][0] = a0.x; k[p][1] = a0.y; k[p][2] = a0.z; k[p][3] = a0.w;
            k[p][4] = a1.x; k[p][5] = a1.y; k[p][6] = a1.z; k[p][7] = a1.w;
        }
#pragma unroll
        for (int p = 0; p < 4; ++p) {
            float sq = 0.f, sk = 0.f;
#pragma unroll
            for (int j = 0; j < 8; ++j) { sq += q[p][j] * q[p][j]; sk += k[p][j] * k[p][j]; }
            float iq = 1.0f / fmaxf(sqrtf(sq), 1e-12f);
            float ik = 1.0f / fmaxf(sqrtf(sk), 1e-12f);
#pragma unroll
            for (int j = 0; j < 8; ++j) { q[p][j] *= iq; k[p][j] *= ik; }
        }
        float rh = sr[h];
        float mbl[4];
#pragma unroll
        for (int p = 0; p < 4; ++p) mbl[p] = mb_s[t * 4 + p];
#pragma unroll
        for (int p = 0; p < 4; ++p) {
#pragma unroll
            for (int pq = 0; pq < 4; ++pq) {
                float d = 0.f;
#pragma unroll
                for (int j = 0; j < 8; ++j) d += q[p][j] * k[pq][j];
                att[p][pq] = d * rh + (mbl[pq] - mbl[p]);
            }
            float mx = fmaxf(fmaxf(att[p][0], att[p][1]), fmaxf(att[p][2], att[p][3]));
            float s = 0.f;
#pragma unroll
            for (int pq = 0; pq < 4; ++pq) { att[p][pq] = __expf(att[p][pq] - mx); s += att[p][pq]; }
            float inv = 1.0f / s;
#pragma unroll
            for (int pq = 0; pq < 4; ++pq) att[p][pq] *= inv;
        }
    }
    STAGE_B(2)
    __syncthreads();                                        // (5)

    // ===== V GEMM =====
    GEMM64(EPI_CF)
    __syncthreads();                                        // (6)

    // mid C: o = att*v -> A (fragment-order, exclusive slots); restage B <- wp
    {
#pragma unroll
        for (int j = 0; j < 8; ++j) {
            int c = h * 8 + j;
            float vv[4];
#pragma unroll
            for (int p = 0; p < 4; ++p) vv[p] = Cf[(t * 4 + p) * 68 + c];
#pragma unroll
            for (int p = 0; p < 4; ++p) {
                float o = att[p][0] * vv[0] + att[p][1] * vv[1] +
                          att[p][2] * vv[2] + att[p][3] * vv[3];
                unsigned short hh, ll;
                bsplit2(o, hh, ll);
                int row = t * 4 + p;
                unsigned off = a_addr(row, c);
                *(unsigned short*)(aHi + off) = hh;
                *(unsigned short*)(aLo + off) = ll;
            }
        }
    }
    STAGE_B(3)
    __syncthreads();                                        // (7)

    // ===== P GEMM -> out staging =====
#define EPI_OUT                                                                 \
        _Pragma("unroll")                                                       \
        for (int mt = 0; mt < 2; ++mt)                                          \
            _Pragma("unroll")                                                   \
            for (int nb = 0; nb < 4; ++nb) {                                    \
                int row = row0 + mt * 16 + gid;                                 \
                int col = col0 + nb * 8 + 2 * tig;                              \
                int tt = row >> 2, p = row & 3;                                 \
                out_s[(p * 64 + col) * 16 + tt]         = acc[mt][nb][0] + sb[col]; \
                out_s[(p * 64 + col + 1) * 16 + tt]     = acc[mt][nb][1] + sb[col + 1]; \
                out_s[(p * 64 + col) * 16 + tt + 2]     = acc[mt][nb][2] + sb[col]; \
                out_s[(p * 64 + col + 1) * 16 + tt + 2] = acc[mt][nb][3] + sb[col + 1]; \
            }

    GEMM64(EPI_OUT)
    __syncthreads();                                        // (8)

    // coalesced writeback
    for (int i4 = tid; i4 < 1024; i4 += 128) {
        int pc = i4 >> 2;
        int t4 = (i4 & 3) * 4;
        int p = pc >> 6, c = pc & 63;
        float4 vv = *(const float4*)(out_s + pc * 16 + t4);
        *(float4*)(out + (size_t)((b * 4 + p) * 64 + c) * HW + pos0 + t4) = vv;
    }
}

// ---------------------------------------------------------------------------
extern "C" void kernel_launch(void* const* d_in, const int* in_sizes, int n_in,
                              void* d_out, int out_size) {
    (void)in_sizes; (void)n_in; (void)out_size;
    const float* x_in   = (const float*)d_in[0];
    const float* mask   = (const float*)d_in[1];
    const float* wq     = (const float*)d_in[2];
    const float* wk     = (const float*)d_in[3];
    const float* wv     = (const float*)d_in[4];
    const float* w_proj = (const float*)d_in[5];
    const float* b_proj = (const float*)d_in[6];
    const float* rescale= (const float*)d_in[7];
    const float* dw_w   = (const float*)d_in[8];
    const float* dw_b   = (const float*)d_in[9];
    const float* pw_w   = (const float*)d_in[10];
    const float* pw_b   = (const float*)d_in[11];
    float* out = (float*)d_out;

    cudaFuncSetAttribute(attn_fused, cudaFuncAttributeMaxDynamicSharedMemorySize,
                         ATTN_SMEM_BYTES);

    mask_kernel3<<<dim3(8, 16), 256>>>(mask, dw_w, dw_b, pw_w, pw_b,
                                       wq, wk, wv, w_proj);
    attn_fused<<<dim3(1024, Bn), 128, ATTN_SMEM_BYTES>>>(
        x_in, b_proj, rescale, out);
}

// round 17
// speedup vs baseline: 2.4925x; 1.1101x over previous
#include <cuda_runtime.h>
#include <cuda_bf16.h>
#include <math.h>

#define Bn 4
#define Pp 4
#define Cc 64
#define NH 8
#define Hh 128
#define Wd 128
#define HW 16384

// scratch (no cudaMalloc allowed)
__device__ float g_mb[16 * HW];          // mask bias per (b,p,pos)
__device__ uint4 g_wFrag[4096];          // 4 matrices x 1024 fragment-quads

// ---------------------------------------------------------------------------
// helpers
// ---------------------------------------------------------------------------
__device__ __forceinline__ void bsplit2(float f, unsigned short& h, unsigned short& l) {
    __nv_bfloat16 hb = __float2bfloat16(f);
    h = __bfloat16_as_ushort(hb);
    l = __bfloat16_as_ushort(__float2bfloat16(f - __bfloat162float(hb)));
}

__device__ __forceinline__ void mma16816(float* c, const unsigned* a,
                                         unsigned b0, unsigned b1) {
    asm volatile(
        "mma.sync.aligned.m16n8k16.row.col.f32.bf16.bf16.f32 "
        "{%0,%1,%2,%3}, {%4,%5,%6,%7}, {%8,%9}, {%0,%1,%2,%3};"
        : "+f"(c[0]), "+f"(c[1]), "+f"(c[2]), "+f"(c[3])
        : "r"(a[0]), "r"(a[1]), "r"(a[2]), "r"(a[3]), "r"(b0), "r"(b1));
}

// fragment-order byte offset for element (row, col) in a 64x64 A tile.
__device__ __forceinline__ unsigned a_addr(int row, int col) {
    int rowgrp = row >> 5, mt = (row >> 4) & 1, gid8 = row & 7, half = (row >> 3) & 1;
    int kk = col >> 4, colhalf = (col >> 3) & 1, tig = (col >> 1) & 3;
    return (unsigned)(((rowgrp * 8 + kk * 2 + mt) * 32 + gid8 * 4 + tig) * 16
                      + (half + 2 * colhalf) * 4 + (col & 1) * 2);
}

// ---------------------------------------------------------------------------
// Kernel 1: mask branch (row-band, 8ch/round) + weight fragment precompute.
// ---------------------------------------------------------------------------
#define TS (18 * 132)
__global__ void __launch_bounds__(256)
mask_kernel3(const float* __restrict__ mask,
             const float* __restrict__ dw_w,
             const float* __restrict__ dw_b,
             const float* __restrict__ pw_w,
             const float* __restrict__ pw_b,
             const float* __restrict__ wq,
             const float* __restrict__ wk,
             const float* __restrict__ wv,
             const float* __restrict__ wp) {
    __shared__ float tilef[8 * TS];
    __shared__ float sdw[Cc][9];
    __shared__ float sdb[Cc];
    __shared__ float swbar[Cc + 1];
    __shared__ float wpart[4][Cc];

    int tid = threadIdx.x;
    int h0 = blockIdx.x * 16;
    int bp = blockIdx.y;

    if (blockIdx.x == 0) {
        int qi = bp * 256 + tid;
        int m = qi >> 10, r = qi & 1023;
        int colgrp = r >> 9, kk = (r >> 7) & 3, nb = (r >> 5) & 3, lane = r & 31;
        int gid = lane >> 2, tig = lane & 3;
        int n = colgrp * 32 + nb * 8 + gid;
        int k0 = kk * 16 + 2 * tig;
        const float* Ws[4] = {wq, wk, wv, wp};
        const float* W = Ws[m];
        float w00 = W[n * 64 + k0],     w01 = W[n * 64 + k0 + 1];
        float w10 = W[n * 64 + k0 + 8], w11 = W[n * 64 + k0 + 9];
        unsigned short h00, l00, h01, l01, h10, l10, h11, l11;
        bsplit2(w00, h00, l00); bsplit2(w01, h01, l01);
        bsplit2(w10, h10, l10); bsplit2(w11, h11, l11);
        uint4 v;
        v.x = (unsigned)h00 | ((unsigned)h01 << 16);
        v.y = (unsigned)h10 | ((unsigned)h11 << 16);
        v.z = (unsigned)l00 | ((unsigned)l01 << 16);
        v.w = (unsigned)l10 | ((unsigned)l11 << 16);
        g_wFrag[m * 1024 + (colgrp * 16 + kk * 4 + nb) * 32 + lane] = v;
    }

    for (int i = tid; i < Cc * 9; i += 256) sdw[i / 9][i % 9] = dw_w[i];
    for (int i = tid; i < Cc; i += 256) sdb[i] = dw_b[i];
    {
        int c = tid & 63, dg = tid >> 6;
        float s = 0.f;
        for (int d = dg * 16; d < dg * 16 + 16; ++d) s += pw_w[d * Cc + c];
        wpart[dg][c] = s;
    }
    if (tid >= 192 && tid < 224) {
        float s = pw_b[tid - 192] + pw_b[tid - 192 + 32];
#pragma unroll
        for (int o = 16; o > 0; o >>= 1)
            s += __shfl_down_sync(0xFFFFFFFFu, s, o);
        if (tid == 192) swbar[Cc] = s * (1.0f / Cc);
    }
    if (tid < 144) {
        int cc = tid / 18, r = tid % 18;
        tilef[cc * TS + r * 132 + 0] = 0.f;
        tilef[cc * TS + r * 132 + 129] = 0.f;
    }
    __syncthreads();
    if (tid < Cc)
        swbar[tid] = (wpart[0][tid] + wpart[1][tid] + wpart[2][tid] + wpart[3][tid]) * (1.0f / Cc);

    const int col = tid & 127;
    const int rowgrp = tid >> 7;
    const float* base = mask + (size_t)bp * Cc * HW;

    float acc[8];
#pragma unroll
    for (int j = 0; j < 8; ++j) acc[j] = 0.f;

    for (int cb = 0; cb < Cc; cb += 8) {
        __syncthreads();
#pragma unroll
        for (int it = 0; it < 9; ++it) {
            int r = it * 2 + rowgrp;
            int gh = h0 + r - 1;
            bool ok = (gh >= 0 && gh < Hh);
            const float* src = base + (size_t)cb * HW + gh * Wd + col;
            float* dst = tilef + r * 132 + col + 1;
#pragma unroll
            for (int cc = 0; cc < 8; ++cc)
                dst[cc * TS] = ok ? src[(size_t)cc * HW] : 0.f;
        }
        __syncthreads();
#pragma unroll
        for (int cc = 0; cc < 8; ++cc) {
            int c = cb + cc;
            const float* tb = tilef + cc * TS + col;
            float w0 = sdw[c][0], w1 = sdw[c][1], w2 = sdw[c][2];
            float w3 = sdw[c][3], w4 = sdw[c][4], w5 = sdw[c][5];
            float w6 = sdw[c][6], w7 = sdw[c][7], w8 = sdw[c][8];
            float bias = sdb[c], wb = swbar[c];
#pragma unroll
            for (int j = 0; j < 8; ++j) {
                int lr = rowgrp * 8 + j;
                const float* t0 = tb + lr * 132;
                float y = bias
                    + t0[0] * w0 + t0[1] * w1 + t0[2] * w2
                    + t0[132] * w3 + t0[133] * w4 + t0[134] * w5
                    + t0[264] * w6 + t0[265] * w7 + t0[266] * w8;
                float g = 0.5f * y * (1.0f + erff(y * 0.70710678118654752f));
                acc[j] += wb * g;
            }
        }
    }
    float bb = swbar[Cc];
#pragma unroll
    for (int j = 0; j < 8; ++j) {
        int lr = rowgrp * 8 + j;
        g_mb[(size_t)bp * HW + (h0 + lr) * Wd + col] = acc[j] + bb;
    }
}

// ---------------------------------------------------------------------------
// Kernel 2: fused 16-token tile, 128 thr, 4 CTAs/SM.
// A in fragment-order smem; B fragments loaded LDG->registers from g_wFrag
// (no B smem traffic at all). smem = aHi 8K + aLo 8K + Cf 17.4K + misc.
// ---------------------------------------------------------------------------
#define SM_AHI 0
#define SM_ALO 8192
#define SM_CF  16384
#define ATTN_SMEM_BYTES 34336

__global__ void __launch_bounds__(128, 4)
attn_fused(const float* __restrict__ x_in,
           const float* __restrict__ b_proj,
           const float* __restrict__ rescale,
           float* __restrict__ out) {
    extern __shared__ char smem[];
    char* aHi = smem + SM_AHI;
    char* aLo = smem + SM_ALO;
    float* Cf    = (float*)(smem + SM_CF);
    float* mb_s  = Cf + 4352;
    float* sb    = mb_s + 64;
    float* sr    = sb + 64;
    float* out_s = Cf;

    int tid = threadIdx.x;
    int b = blockIdx.y;
    int pos0 = blockIdx.x * 16;

    // stage A: batch 8 LDG.128, then bsplit into fragment-order
    {
        float4 xr[8];
#pragma unroll
        for (int s = 0; s < 8; ++s) {
            int i4 = tid + s * 128;
            int pc = i4 >> 2;
            int t4 = (i4 & 3) * 4;
            int p = pc >> 6, c = pc & 63;
            xr[s] = *(const float4*)(x_in + (size_t)((b * 4 + p) * 64 + c) * HW + pos0 + t4);
        }
#pragma unroll
        for (int s = 0; s < 8; ++s) {
            int i4 = tid + s * 128;
            int pc = i4 >> 2;
            int t4 = (i4 & 3) * 4;
            int p = pc >> 6, c = pc & 63;
            float xs[4] = {xr[s].x, xr[s].y, xr[s].z, xr[s].w};
#pragma unroll
            for (int j = 0; j < 4; ++j) {
                int row = (t4 + j) * 4 + p;
                unsigned short hh, ll;
                bsplit2(xs[j], hh, ll);
                unsigned off = a_addr(row, c);
                *(unsigned short*)(aHi + off) = hh;
                *(unsigned short*)(aLo + off) = ll;
            }
        }
    }
    if (tid < 64) {
        int p = tid >> 4, t = tid & 15;
        mb_s[t * 4 + p] = g_mb[(size_t)(b * 4 + p) * HW + pos0 + t];
        sb[tid] = b_proj[tid];
    }
    if (tid < 8) sr[tid] = rescale[tid];
    __syncthreads();                                        // (1)

    int lane = tid & 31, wid = tid >> 5;
    int gid = lane >> 2, tig = lane & 3;
    const int t = tid >> 3, h = tid & 7;
    int wm = wid & 1, wn = wid >> 1;
    int row0 = wm * 32, col0 = wn * 32;

    // per-thread B fragment base for matrix m: g_wFrag + m*1024 + wn*512 + lane
#define GEMM64(m, EPILOG)                                                       \
    {                                                                           \
        const uint4* bsrc = g_wFrag + (m) * 1024 + wn * 512 + lane;             \
        float acc[2][4][4];                                                     \
        _Pragma("unroll")                                                       \
        for (int mt = 0; mt < 2; ++mt)                                          \
            _Pragma("unroll")                                                   \
            for (int nb = 0; nb < 4; ++nb)                                      \
                _Pragma("unroll")                                               \
                for (int i = 0; i < 4; ++i) acc[mt][nb][i] = 0.f;               \
        uint4 bq[4];                                                            \
        _Pragma("unroll")                                                       \
        for (int nb = 0; nb < 4; ++nb) bq[nb] = bsrc[nb * 32];                  \
        _Pragma("unroll")                                                       \
        for (int kk = 0; kk < 4; ++kk) {                                        \
            uint4 bqn[4];                                                       \
            if (kk < 3) {                                                       \
                _Pragma("unroll")                                               \
                for (int nb = 0; nb < 4; ++nb)                                  \
                    bqn[nb] = bsrc[(kk + 1) * 128 + nb * 32];                   \
            }                                                                   \
            uint4 vh[2], vl[2];                                                 \
            _Pragma("unroll")                                                   \
            for (int mt = 0; mt < 2; ++mt) {                                    \
                unsigned ao = (unsigned)(((wm * 8 + kk * 2 + mt) * 32 + lane) * 16); \
                vh[mt] = *(const uint4*)(aHi + ao);                             \
                vl[mt] = *(const uint4*)(aLo + ao);                             \
            }                                                                   \
            _Pragma("unroll")                                                   \
            for (int nb = 0; nb < 4; ++nb) {                                    \
                _Pragma("unroll")                                               \
                for (int mt = 0; mt < 2; ++mt) {                                \
                    mma16816(acc[mt][nb], (const unsigned*)&vh[mt], bq[nb].x, bq[nb].y); \
                    mma16816(acc[mt][nb], (const unsigned*)&vh[mt], bq[nb].z, bq[nb].w); \
                    mma16816(acc[mt][nb], (const unsigned*)&vl[mt], bq[nb].x, bq[nb].y); \
                }                                                               \
            }                                                                   \
            _Pragma("unroll")                                                   \
            for (int nb = 0; nb < 4; ++nb) bq[nb] = bqn[nb];                    \
        }                                                                       \
        EPILOG                                                                  \
    }

#define EPI_CF                                                                  \
        _Pragma("unroll")                                                       \
        for (int mt = 0; mt < 2; ++mt)                                          \
            _Pragma("unroll")                                                   \
            for (int nb = 0; nb < 4; ++nb) {                                    \
                int row = row0 + mt * 16 + gid;                                 \
                int col = col0 + nb * 8 + 2 * tig;                              \
                float* dst = Cf + row * 68 + col;                               \
                *(float2*)dst = make_float2(acc[mt][nb][0], acc[mt][nb][1]);    \
                *(float2*)(dst + 8 * 68) = make_float2(acc[mt][nb][2], acc[mt][nb][3]); \
            }

    // ===== Q GEMM =====
    GEMM64(0, EPI_CF)
    __syncthreads();                                        // (2)

    // mid A: read q -> regs
    float q[4][8];
#pragma unroll
    for (int p = 0; p < 4; ++p) {
        const float4* cr = (const float4*)(Cf + (t * 4 + p) * 68 + h * 8);
        float4 a0 = cr[0], a1 = cr[1];
        q[p][0] = a0.x; q[p][1] = a0.y; q[p][2] = a0.z; q[p][3] = a0.w;
        q[p][4] = a1.x; q[p][5] = a1.y; q[p][6] = a1.z; q[p][7] = a1.w;
    }
    __syncthreads();                                        // (3)

    // ===== K GEMM =====
    GEMM64(1, EPI_CF)
    __syncthreads();                                        // (4)

    // mid B: read k, normalize, softmax -> att
    float att[4][4];
    {
        float k[4][8];
#pragma unroll
        for (int p = 0; p < 4; ++p) {
            const float4* cr = (const float4*)(Cf + (t * 4 + p) * 68 + h * 8);
            float4 a0 = cr[0], a1 = cr[1];
            k[p][0] = a0.x; k[p][1] = a0.y; k[p][2] = a0.z; k[p][3] = a0.w;
            k[p][4] = a1.x; k[p][5] = a1.y; k[p][6] = a1.z; k[p][7] = a1.w;
        }
#pragma unroll
        for (int p = 0; p < 4; ++p) {
            float sq = 0.f, sk = 0.f;
#pragma unroll
            for (int j = 0; j < 8; ++j) { sq += q[p][j] * q[p][j]; sk += k[p][j] * k[p][j]; }
            float iq = 1.0f / fmaxf(sqrtf(sq), 1e-12f);
            float ik = 1.0f / fmaxf(sqrtf(sk), 1e-12f);
#pragma unroll
            for (int j = 0; j < 8; ++j) { q[p][j] *= iq; k[p][j] *= ik; }
        }
        float rh = sr[h];
        float mbl[4];
#pragma unroll
        for (int p = 0; p < 4; ++p) mbl[p] = mb_s[t * 4 + p];
#pragma unroll
        for (int p = 0; p < 4; ++p) {
#pragma unroll
            for (int pq = 0; pq < 4; ++pq) {
                float d = 0.f;
#pragma unroll
                for (int j = 0; j < 8; ++j) d += q[p][j] * k[pq][j];
                att[p][pq] = d * rh + (mbl[pq] - mbl[p]);
            }
            float mx = fmaxf(fmaxf(att[p][0], att[p][1]), fmaxf(att[p][2], att[p][3]));
            float s = 0.f;
#pragma unroll
            for (int pq = 0; pq < 4; ++pq) { att[p][pq] = __expf(att[p][pq] - mx); s += att[p][pq]; }
            float inv = 1.0f / s;
#pragma unroll
            for (int pq = 0; pq < 4; ++pq) att[p][pq] *= inv;
        }
    }
    __syncthreads();                                        // (5)

    // ===== V GEMM =====
    GEMM64(2, EPI_CF)
    __syncthreads();                                        // (6)

    // mid C: o = att*v -> A (fragment-order, exclusive slots)
    {
#pragma unroll
        for (int j = 0; j < 8; ++j) {
            int c = h * 8 + j;
            float vv[4];
#pragma unroll
            for (int p = 0; p < 4; ++p) vv[p] = Cf[(t * 4 + p) * 68 + c];
#pragma unroll
            for (int p = 0; p < 4; ++p) {
                float o = att[p][0] * vv[0] + att[p][1] * vv[1] +
                          att[p][2] * vv[2] + att[p][3] * vv[3];
                unsigned short hh, ll;
                bsplit2(o, hh, ll);
                int row = t * 4 + p;
                unsigned off = a_addr(row, c);
                *(unsigned short*)(aHi + off) = hh;
                *(unsigned short*)(aLo + off) = ll;
            }
        }
    }
    __syncthreads();                                        // (7)

    // ===== P GEMM -> out staging =====
#define EPI_OUT                                                                 \
        _Pragma("unroll")                                                       \
        for (int mt = 0; mt < 2; ++mt)                                          \
            _Pragma("unroll")                                                   \
            for (int nb = 0; nb < 4; ++nb) {                                    \
                int row = row0 + mt * 16 + gid;                                 \
                int col = col0 + nb * 8 + 2 * tig;                              \
                int tt = row >> 2, p = row & 3;                                 \
                out_s[(p * 64 + col) * 16 + tt]         = acc[mt][nb][0] + sb[col]; \
                out_s[(p * 64 + col + 1) * 16 + tt]     = acc[mt][nb][1] + sb[col + 1]; \
                out_s[(p * 64 + col) * 16 + tt + 2]     = acc[mt][nb][2] + sb[col]; \
                out_s[(p * 64 + col + 1) * 16 + tt + 2] = acc[mt][nb][3] + sb[col + 1]; \
            }

    GEMM64(3, EPI_OUT)
    __syncthreads();                                        // (8)

    // coalesced writeback
    for (int i4 = tid; i4 < 1024; i4 += 128) {
        int pc = i4 >> 2;
        int t4 = (i4 & 3) * 4;
        int p = pc >> 6, c = pc & 63;
        float4 vv = *(const float4*)(out_s + pc * 16 + t4);
        *(float4*)(out + (size_t)((b * 4 + p) * 64 + c) * HW + pos0 + t4) = vv;
    }
}

// ---------------------------------------------------------------------------
extern "C" void kernel_launch(void* const* d_in, const int* in_sizes, int n_in,
                              void* d_out, int out_size) {
    (void)in_sizes; (void)n_in; (void)out_size;
    const float* x_in   = (const float*)d_in[0];
    const float* mask   = (const float*)d_in[1];
    const float* wq     = (const float*)d_in[2];
    const float* wk     = (const float*)d_in[3];
    const float* wv     = (const float*)d_in[4];
    const float* w_proj = (const float*)d_in[5];
    const float* b_proj = (const float*)d_in[6];
    const float* rescale= (const float*)d_in[7];
    const float* dw_w   = (const float*)d_in[8];
    const float* dw_b   = (const float*)d_in[9];
    const float* pw_w   = (const float*)d_in[10];
    const float* pw_b   = (const float*)d_in[11];
    float* out = (float*)d_out;

    cudaFuncSetAttribute(attn_fused, cudaFuncAttributeMaxDynamicSharedMemorySize,
                         ATTN_SMEM_BYTES);

    mask_kernel3<<<dim3(8, 16), 256>>>(mask, dw_w, dw_b, pw_w, pw_b,
                                       wq, wk, wv, w_proj);
    attn_fused<<<dim3(1024, Bn), 128, ATTN_SMEM_BYTES>>>(
        x_in, b_proj, rescale, out);
}